// round 2
// baseline (speedup 1.0000x reference)
#include <cuda_runtime.h>
#include <math.h>

#define SS 512
#define II 384
#define CM 64
#define CZ 128
#define NH 8
#define NC 32
#define HC 256

// Scratch (device globals: allocation-free rule)
__device__ float g_v[SS*II*HC];      // v[s][j][h*32+c]
__device__ float g_gate[SS*II*HC];   // sigmoid(msa_n @ W_gate)
__device__ float g_bias[II*II*NH];   // bias[i][j][h] pre-softmax
__device__ float g_w[NH*II*II];      // softmaxed weights, [h][i][j]
__device__ float g_o[SS*II*HC];      // gate * weighted average

// ---------------------------------------------------------------------------
// K1: msa LN + V + gate.  rows = S*I = 196608.  Block: 256 thr, 96 rows.
// W_v/W_gate columns cached in registers (128 regs/thread).
// ---------------------------------------------------------------------------
__global__ __launch_bounds__(256) void k1_msa(
    const float* __restrict__ msa,
    const float* __restrict__ lng, const float* __restrict__ lnb,
    const float* __restrict__ Wv,  const float* __restrict__ Wg)
{
    __shared__ float sy[8][CM];
    const int tid = threadIdx.x;
    const int warp = tid >> 5, lane = tid & 31;

    float wv[CM], wg[CM];
#pragma unroll
    for (int c = 0; c < CM; c++) {
        wv[c] = Wv[c*HC + tid];
        wg[c] = Wg[c*HC + tid];
    }
    const float g0 = lng[lane*2], g1 = lng[lane*2+1];
    const float b0 = lnb[lane*2], b1 = lnb[lane*2+1];

    const int base = blockIdx.x * 96;
#pragma unroll 1
    for (int it = 0; it < 12; it++) {
        const int row = base + it*8 + warp;
        const float2 x = ((const float2*)(msa + (size_t)row*CM))[lane];
        float s1 = x.x + x.y;
        float s2 = x.x*x.x + x.y*x.y;
#pragma unroll
        for (int off = 16; off; off >>= 1) {
            s1 += __shfl_xor_sync(0xffffffffu, s1, off);
            s2 += __shfl_xor_sync(0xffffffffu, s2, off);
        }
        const float mu  = s1 * (1.f/64.f);
        const float var = s2 * (1.f/64.f) - mu*mu;
        const float rs  = rsqrtf(var + 1e-5f);
        sy[warp][lane*2]   = (x.x - mu)*rs*g0 + b0;
        sy[warp][lane*2+1] = (x.y - mu)*rs*g1 + b1;
        __syncthreads();

#pragma unroll 1
        for (int r = 0; r < 8; r++) {
            float av = 0.f, ag = 0.f;
#pragma unroll
            for (int c = 0; c < CM; c++) {
                const float y = sy[r][c];
                av = fmaf(y, wv[c], av);
                ag = fmaf(y, wg[c], ag);
            }
            const size_t orow = (size_t)(base + it*8 + r) * HC;
            g_v[orow + tid]    = av;
            g_gate[orow + tid] = 1.f / (1.f + expf(-ag));
        }
        __syncthreads();
    }
}

// ---------------------------------------------------------------------------
// K2a: pair LN + bias matvec.  rows = I*I = 147456, 1 warp per row.
// ---------------------------------------------------------------------------
__global__ __launch_bounds__(256) void k2_bias(
    const float* __restrict__ pair,
    const float* __restrict__ lng, const float* __restrict__ lnb,
    const float* __restrict__ Wb)
{
    const int tid = threadIdx.x, warp = tid >> 5, lane = tid & 31;
    const int row = blockIdx.x * 8 + warp;

    const float4 x = ((const float4*)(pair + (size_t)row*CZ))[lane];
    float s1 = x.x + x.y + x.z + x.w;
    float s2 = x.x*x.x + x.y*x.y + x.z*x.z + x.w*x.w;
#pragma unroll
    for (int off = 16; off; off >>= 1) {
        s1 += __shfl_xor_sync(0xffffffffu, s1, off);
        s2 += __shfl_xor_sync(0xffffffffu, s2, off);
    }
    const float mu  = s1 * (1.f/128.f);
    const float var = s2 * (1.f/128.f) - mu*mu;
    const float rs  = rsqrtf(var + 1e-5f);

    const float4 gg = ((const float4*)lng)[lane];
    const float4 bb = ((const float4*)lnb)[lane];
    float y[4];
    y[0] = (x.x - mu)*rs*gg.x + bb.x;
    y[1] = (x.y - mu)*rs*gg.y + bb.y;
    y[2] = (x.z - mu)*rs*gg.z + bb.z;
    y[3] = (x.w - mu)*rs*gg.w + bb.w;

    float acc0=0,acc1=0,acc2=0,acc3=0,acc4=0,acc5=0,acc6=0,acc7=0;
#pragma unroll
    for (int q = 0; q < 4; q++) {
        const float yq = y[q];
        const float4* wrow = (const float4*)(Wb + (size_t)(4*lane+q)*NH);
        const float4 w0 = wrow[0], w1 = wrow[1];
        acc0 = fmaf(yq, w0.x, acc0); acc1 = fmaf(yq, w0.y, acc1);
        acc2 = fmaf(yq, w0.z, acc2); acc3 = fmaf(yq, w0.w, acc3);
        acc4 = fmaf(yq, w1.x, acc4); acc5 = fmaf(yq, w1.y, acc5);
        acc6 = fmaf(yq, w1.z, acc6); acc7 = fmaf(yq, w1.w, acc7);
    }
#pragma unroll
    for (int off = 16; off; off >>= 1) {
        acc0 += __shfl_xor_sync(0xffffffffu, acc0, off);
        acc1 += __shfl_xor_sync(0xffffffffu, acc1, off);
        acc2 += __shfl_xor_sync(0xffffffffu, acc2, off);
        acc3 += __shfl_xor_sync(0xffffffffu, acc3, off);
        acc4 += __shfl_xor_sync(0xffffffffu, acc4, off);
        acc5 += __shfl_xor_sync(0xffffffffu, acc5, off);
        acc6 += __shfl_xor_sync(0xffffffffu, acc6, off);
        acc7 += __shfl_xor_sync(0xffffffffu, acc7, off);
    }
    if (lane == 0) {
        float4* op = (float4*)(g_bias + (size_t)row*NH);
        op[0] = make_float4(acc0, acc1, acc2, acc3);
        op[1] = make_float4(acc4, acc5, acc6, acc7);
    }
}

// ---------------------------------------------------------------------------
// K2b: softmax over j per (i,h); write transposed layout g_w[h][i][j].
// One block per i; warp h handles head h.
// ---------------------------------------------------------------------------
__global__ __launch_bounds__(256) void k2_softmax()
{
    __shared__ float sb[II][NH+1];
    const int tid = threadIdx.x;
    const int i = blockIdx.x;
    for (int idx = tid; idx < II*NH; idx += 256)
        sb[idx/NH][idx%NH] = g_bias[(size_t)i*II*NH + idx];
    __syncthreads();

    const int h = tid >> 5, lane = tid & 31;
    float v[12];
    float m = -1e30f;
#pragma unroll
    for (int q = 0; q < 12; q++) {
        v[q] = sb[lane + 32*q][h];
        m = fmaxf(m, v[q]);
    }
#pragma unroll
    for (int off = 16; off; off >>= 1)
        m = fmaxf(m, __shfl_xor_sync(0xffffffffu, m, off));
    float s = 0.f;
    float e[12];
#pragma unroll
    for (int q = 0; q < 12; q++) {
        e[q] = expf(v[q] - m);
        s += e[q];
    }
#pragma unroll
    for (int off = 16; off; off >>= 1)
        s += __shfl_xor_sync(0xffffffffu, s, off);
    const float inv = 1.f / s;
    float* wout = g_w + (size_t)h*II*II + (size_t)i*II;
#pragma unroll
    for (int q = 0; q < 12; q++)
        wout[lane + 32*q] = e[q] * inv;
}

// ---------------------------------------------------------------------------
// K3: per-h GEMM  C[i, n] = sum_j w[h][i][j] * v[s(n)][j][h*32+c(n)],
// n = s*32+c over N = S*32 = 16384.  Epilogue: multiply gate, store g_o.
// Tile 64x64x16, 256 threads, 4x4 micro-tile.
// grid = (256, 6, 8)
// ---------------------------------------------------------------------------
__global__ __launch_bounds__(256) void k3_einsum()
{
    __shared__ __align__(16) float sA[16][68];   // [k][m]
    __shared__ __align__(16) float sB[16][64];   // [k][n]
    const int tid = threadIdx.x;
    const int h  = blockIdx.z;
    const int i0 = blockIdx.y * 64;
    const int n0 = blockIdx.x * 64;
    const int s0 = n0 >> 5;
    const int tx = tid & 15, ty = tid >> 4;

    const int lm  = tid >> 2;            // A tile row (m), 0..63
    const int lk4 = (tid & 3) * 4;       // A tile k start
    const int bn4 = (tid & 15) * 4;      // B tile n start
    const int bk  = tid >> 4;            // B tile k, 0..15
    const int bs  = s0 + (bn4 >> 5);
    const int bc  = bn4 & 31;

    const float* Aptr = g_w + (size_t)h*II*II + (size_t)(i0+lm)*II + lk4;
    const float* Bptr = g_v + (size_t)bs*II*HC + (size_t)h*32 + bc;

    float acc[4][4];
#pragma unroll
    for (int a = 0; a < 4; a++)
#pragma unroll
        for (int b = 0; b < 4; b++) acc[a][b] = 0.f;

    for (int j0 = 0; j0 < II; j0 += 16) {
        const float4 a4 = *(const float4*)(Aptr + j0);
        const float4 b4 = *(const float4*)(Bptr + (size_t)(j0 + bk)*HC);
        __syncthreads();
        sA[lk4+0][lm] = a4.x;
        sA[lk4+1][lm] = a4.y;
        sA[lk4+2][lm] = a4.z;
        sA[lk4+3][lm] = a4.w;
        *(float4*)&sB[bk][bn4] = b4;
        __syncthreads();
#pragma unroll
        for (int k = 0; k < 16; k++) {
            const float4 av = *(const float4*)&sA[k][ty*4];
            const float4 bv = *(const float4*)&sB[k][tx*4];
            acc[0][0] = fmaf(av.x, bv.x, acc[0][0]);
            acc[0][1] = fmaf(av.x, bv.y, acc[0][1]);
            acc[0][2] = fmaf(av.x, bv.z, acc[0][2]);
            acc[0][3] = fmaf(av.x, bv.w, acc[0][3]);
            acc[1][0] = fmaf(av.y, bv.x, acc[1][0]);
            acc[1][1] = fmaf(av.y, bv.y, acc[1][1]);
            acc[1][2] = fmaf(av.y, bv.z, acc[1][2]);
            acc[1][3] = fmaf(av.y, bv.w, acc[1][3]);
            acc[2][0] = fmaf(av.z, bv.x, acc[2][0]);
            acc[2][1] = fmaf(av.z, bv.y, acc[2][1]);
            acc[2][2] = fmaf(av.z, bv.z, acc[2][2]);
            acc[2][3] = fmaf(av.z, bv.w, acc[2][3]);
            acc[3][0] = fmaf(av.w, bv.x, acc[3][0]);
            acc[3][1] = fmaf(av.w, bv.y, acc[3][1]);
            acc[3][2] = fmaf(av.w, bv.z, acc[3][2]);
            acc[3][3] = fmaf(av.w, bv.w, acc[3][3]);
        }
    }

#pragma unroll
    for (int a = 0; a < 4; a++) {
        const int ig = i0 + ty*4 + a;
#pragma unroll
        for (int b = 0; b < 4; b++) {
            const int nn = tx*4 + b;
            const int s  = s0 + (nn >> 5);
            const int c  = nn & 31;
            const size_t idx = ((size_t)s*II + ig)*HC + h*32 + c;
            g_o[idx] = acc[a][b] * g_gate[idx];
        }
    }
}

// ---------------------------------------------------------------------------
// K4: out = g_o @ W_out.  M = 196608, K = 256, N = 64.
// Tile 64x64x16, 256 threads, 4x4 micro-tile.  grid = 3072.
// ---------------------------------------------------------------------------
__global__ __launch_bounds__(256) void k4_out(
    const float* __restrict__ Wout, float* __restrict__ out)
{
    __shared__ __align__(16) float sA[16][68];
    __shared__ __align__(16) float sB[16][64];
    const int tid = threadIdx.x;
    const int r0 = blockIdx.x * 64;
    const int tx = tid & 15, ty = tid >> 4;
    const int lm  = tid >> 2;
    const int lk4 = (tid & 3) * 4;
    const int bn4 = (tid & 15) * 4;
    const int bk  = tid >> 4;

    float acc[4][4];
#pragma unroll
    for (int a = 0; a < 4; a++)
#pragma unroll
        for (int b = 0; b < 4; b++) acc[a][b] = 0.f;

    for (int k0 = 0; k0 < HC; k0 += 16) {
        const float4 a4 = *(const float4*)(g_o + (size_t)(r0+lm)*HC + k0 + lk4);
        const float4 b4 = *(const float4*)(Wout + (size_t)(k0+bk)*CM + bn4);
        __syncthreads();
        sA[lk4+0][lm] = a4.x;
        sA[lk4+1][lm] = a4.y;
        sA[lk4+2][lm] = a4.z;
        sA[lk4+3][lm] = a4.w;
        *(float4*)&sB[bk][bn4] = b4;
        __syncthreads();
#pragma unroll
        for (int k = 0; k < 16; k++) {
            const float4 av = *(const float4*)&sA[k][ty*4];
            const float4 bv = *(const float4*)&sB[k][tx*4];
            acc[0][0] = fmaf(av.x, bv.x, acc[0][0]);
            acc[0][1] = fmaf(av.x, bv.y, acc[0][1]);
            acc[0][2] = fmaf(av.x, bv.z, acc[0][2]);
            acc[0][3] = fmaf(av.x, bv.w, acc[0][3]);
            acc[1][0] = fmaf(av.y, bv.x, acc[1][0]);
            acc[1][1] = fmaf(av.y, bv.y, acc[1][1]);
            acc[1][2] = fmaf(av.y, bv.z, acc[1][2]);
            acc[1][3] = fmaf(av.y, bv.w, acc[1][3]);
            acc[2][0] = fmaf(av.z, bv.x, acc[2][0]);
            acc[2][1] = fmaf(av.z, bv.y, acc[2][1]);
            acc[2][2] = fmaf(av.z, bv.z, acc[2][2]);
            acc[2][3] = fmaf(av.z, bv.w, acc[2][3]);
            acc[3][0] = fmaf(av.w, bv.x, acc[3][0]);
            acc[3][1] = fmaf(av.w, bv.y, acc[3][1]);
            acc[3][2] = fmaf(av.w, bv.z, acc[3][2]);
            acc[3][3] = fmaf(av.w, bv.w, acc[3][3]);
        }
    }

#pragma unroll
    for (int a = 0; a < 4; a++) {
        float* op = out + (size_t)(r0 + ty*4 + a)*CM + tx*4;
        *(float4*)op = make_float4(acc[a][0], acc[a][1], acc[a][2], acc[a][3]);
    }
}

// ---------------------------------------------------------------------------
extern "C" void kernel_launch(void* const* d_in, const int* in_sizes, int n_in,
                              void* d_out, int out_size)
{
    const float* msa      = (const float*)d_in[0];
    const float* pair     = (const float*)d_in[1];
    const float* ln_msa_g = (const float*)d_in[2];
    const float* ln_msa_b = (const float*)d_in[3];
    const float* ln_pair_g= (const float*)d_in[4];
    const float* ln_pair_b= (const float*)d_in[5];
    const float* W_v      = (const float*)d_in[6];
    const float* W_bias   = (const float*)d_in[7];
    const float* W_gate   = (const float*)d_in[8];
    const float* W_out    = (const float*)d_in[9];
    float* out = (float*)d_out;

    k1_msa<<<2048, 256>>>(msa, ln_msa_g, ln_msa_b, W_v, W_gate);
    k2_bias<<<18432, 256>>>(pair, ln_pair_g, ln_pair_b, W_bias);
    k2_softmax<<<II, 256>>>();
    k3_einsum<<<dim3(256, 6, 8), 256>>>();
    k4_out<<<3072, 256>>>(W_out, out);
}

// round 8
// speedup vs baseline: 1.0919x; 1.0919x over previous
#include <cuda_runtime.h>
#include <math.h>

#define SS 512
#define II 384
#define CM 64
#define CZ 128
#define NH 8
#define NC 32
#define HC 256

// Scratch (device globals: allocation-free rule)
__device__ float g_v[SS*II*HC];      // v[s][j][h*32+c]
__device__ float g_gate[SS*II*HC];   // sigmoid(msa_n @ W_gate)
__device__ float g_bias[II*II*NH];   // bias[i][j][h] pre-softmax
__device__ float g_w[NH*II*II];      // softmaxed weights, [h][i][j]
__device__ float g_o[SS*II*HC];      // gate * weighted average

// ---------------------------------------------------------------------------
// f32x2 packed-math helpers (Blackwell dual fp32 path; PTX-only)
// ---------------------------------------------------------------------------
__device__ __forceinline__ void fma2(unsigned long long& d,
                                     unsigned long long a,
                                     unsigned long long b)
{
    asm("fma.rn.f32x2 %0, %1, %2, %0;" : "+l"(d) : "l"(a), "l"(b));
}
__device__ __forceinline__ unsigned long long pack_dup(float x)
{
    unsigned long long r;
    asm("mov.b64 %0, {%1, %1};" : "=l"(r) : "r"(__float_as_uint(x)));
    return r;
}
__device__ __forceinline__ unsigned long long pack2(float lo, float hi)
{
    unsigned long long r;
    asm("mov.b64 %0, {%1, %2};" : "=l"(r)
        : "r"(__float_as_uint(lo)), "r"(__float_as_uint(hi)));
    return r;
}
__device__ __forceinline__ float2 unpk(unsigned long long v)
{
    float2 r;
    asm("mov.b64 {%0, %1}, %2;" : "=f"(r.x), "=f"(r.y) : "l"(v));
    return r;
}
__device__ __forceinline__ void add2(unsigned long long& d, unsigned long long a)
{
    asm("add.rn.f32x2 %0, %0, %1;" : "+l"(d) : "l"(a));
}

// ---------------------------------------------------------------------------
// K1: msa LN + V + gate.  rows = S*I = 196608.  Block: 256 thr, 96 rows.
// Packed weights: w2[c] = (Wv[c][tid], Wg[c][tid]).  sy stored duplicated so
// LDS.128 yields two dup-pairs directly (broadcast, 1 wf).
// ---------------------------------------------------------------------------
__global__ __launch_bounds__(256) void k1_msa(
    const float* __restrict__ msa,
    const float* __restrict__ lng, const float* __restrict__ lnb,
    const float* __restrict__ Wv,  const float* __restrict__ Wg)
{
    __shared__ __align__(16) float2 sy2[8][CM];   // duplicated LN rows
    const int tid = threadIdx.x;
    const int warp = tid >> 5, lane = tid & 31;

    unsigned long long w2[CM];
#pragma unroll
    for (int c = 0; c < CM; c++)
        w2[c] = pack2(Wv[c*HC + tid], Wg[c*HC + tid]);

    const float g0 = lng[lane*2], g1 = lng[lane*2+1];
    const float b0 = lnb[lane*2], b1 = lnb[lane*2+1];

    const int base = blockIdx.x * 96;
#pragma unroll 1
    for (int it = 0; it < 12; it++) {
        const int row = base + it*8 + warp;
        const float2 x = ((const float2*)(msa + (size_t)row*CM))[lane];
        float s1 = x.x + x.y;
        float s2 = x.x*x.x + x.y*x.y;
#pragma unroll
        for (int off = 16; off; off >>= 1) {
            s1 += __shfl_xor_sync(0xffffffffu, s1, off);
            s2 += __shfl_xor_sync(0xffffffffu, s2, off);
        }
        const float mu  = s1 * (1.f/64.f);
        const float var = s2 * (1.f/64.f) - mu*mu;
        const float rs  = rsqrtf(var + 1e-5f);
        const float y0 = (x.x - mu)*rs*g0 + b0;
        const float y1 = (x.y - mu)*rs*g1 + b1;
        sy2[warp][lane*2]   = make_float2(y0, y0);
        sy2[warp][lane*2+1] = make_float2(y1, y1);
        __syncthreads();

#pragma unroll 1
        for (int r = 0; r < 8; r++) {
            unsigned long long a0 = 0ull, a1 = 0ull, a2 = 0ull, a3 = 0ull;
#pragma unroll
            for (int c = 0; c < CM; c += 4) {
                const ulonglong2 q0 = *(const ulonglong2*)&sy2[r][c];
                const ulonglong2 q1 = *(const ulonglong2*)&sy2[r][c+2];
                fma2(a0, q0.x, w2[c]);
                fma2(a1, q0.y, w2[c+1]);
                fma2(a2, q1.x, w2[c+2]);
                fma2(a3, q1.y, w2[c+3]);
            }
            add2(a0, a1); add2(a2, a3); add2(a0, a2);
            const float2 res = unpk(a0);
            const size_t orow = (size_t)(base + it*8 + r) * HC;
            g_v[orow + tid]    = res.x;
            g_gate[orow + tid] = 1.f / (1.f + expf(-res.y));
        }
        __syncthreads();
    }
}

// ---------------------------------------------------------------------------
// K2a: pair LN + bias matvec.  rows = I*I = 147456, 1 warp per row.
// ---------------------------------------------------------------------------
__global__ __launch_bounds__(256) void k2_bias(
    const float* __restrict__ pair,
    const float* __restrict__ lng, const float* __restrict__ lnb,
    const float* __restrict__ Wb)
{
    const int tid = threadIdx.x, warp = tid >> 5, lane = tid & 31;
    const int row = blockIdx.x * 8 + warp;

    const float4 x = ((const float4*)(pair + (size_t)row*CZ))[lane];
    float s1 = x.x + x.y + x.z + x.w;
    float s2 = x.x*x.x + x.y*x.y + x.z*x.z + x.w*x.w;
#pragma unroll
    for (int off = 16; off; off >>= 1) {
        s1 += __shfl_xor_sync(0xffffffffu, s1, off);
        s2 += __shfl_xor_sync(0xffffffffu, s2, off);
    }
    const float mu  = s1 * (1.f/128.f);
    const float var = s2 * (1.f/128.f) - mu*mu;
    const float rs  = rsqrtf(var + 1e-5f);

    const float4 gg = ((const float4*)lng)[lane];
    const float4 bb = ((const float4*)lnb)[lane];
    float y[4];
    y[0] = (x.x - mu)*rs*gg.x + bb.x;
    y[1] = (x.y - mu)*rs*gg.y + bb.y;
    y[2] = (x.z - mu)*rs*gg.z + bb.z;
    y[3] = (x.w - mu)*rs*gg.w + bb.w;

    float acc0=0,acc1=0,acc2=0,acc3=0,acc4=0,acc5=0,acc6=0,acc7=0;
#pragma unroll
    for (int q = 0; q < 4; q++) {
        const float yq = y[q];
        const float4* wrow = (const float4*)(Wb + (size_t)(4*lane+q)*NH);
        const float4 w0 = wrow[0], w1 = wrow[1];
        acc0 = fmaf(yq, w0.x, acc0); acc1 = fmaf(yq, w0.y, acc1);
        acc2 = fmaf(yq, w0.z, acc2); acc3 = fmaf(yq, w0.w, acc3);
        acc4 = fmaf(yq, w1.x, acc4); acc5 = fmaf(yq, w1.y, acc5);
        acc6 = fmaf(yq, w1.z, acc6); acc7 = fmaf(yq, w1.w, acc7);
    }
#pragma unroll
    for (int off = 16; off; off >>= 1) {
        acc0 += __shfl_xor_sync(0xffffffffu, acc0, off);
        acc1 += __shfl_xor_sync(0xffffffffu, acc1, off);
        acc2 += __shfl_xor_sync(0xffffffffu, acc2, off);
        acc3 += __shfl_xor_sync(0xffffffffu, acc3, off);
        acc4 += __shfl_xor_sync(0xffffffffu, acc4, off);
        acc5 += __shfl_xor_sync(0xffffffffu, acc5, off);
        acc6 += __shfl_xor_sync(0xffffffffu, acc6, off);
        acc7 += __shfl_xor_sync(0xffffffffu, acc7, off);
    }
    if (lane == 0) {
        float4* op = (float4*)(g_bias + (size_t)row*NH);
        op[0] = make_float4(acc0, acc1, acc2, acc3);
        op[1] = make_float4(acc4, acc5, acc6, acc7);
    }
}

// ---------------------------------------------------------------------------
// K2b: softmax over j per (i,h); write transposed layout g_w[h][i][j].
// ---------------------------------------------------------------------------
__global__ __launch_bounds__(256) void k2_softmax()
{
    __shared__ float sb[II][NH+1];
    const int tid = threadIdx.x;
    const int i = blockIdx.x;
    for (int idx = tid; idx < II*NH; idx += 256)
        sb[idx/NH][idx%NH] = g_bias[(size_t)i*II*NH + idx];
    __syncthreads();

    const int h = tid >> 5, lane = tid & 31;
    float v[12];
    float m = -1e30f;
#pragma unroll
    for (int q = 0; q < 12; q++) {
        v[q] = sb[lane + 32*q][h];
        m = fmaxf(m, v[q]);
    }
#pragma unroll
    for (int off = 16; off; off >>= 1)
        m = fmaxf(m, __shfl_xor_sync(0xffffffffu, m, off));
    float s = 0.f;
    float e[12];
#pragma unroll
    for (int q = 0; q < 12; q++) {
        e[q] = expf(v[q] - m);
        s += e[q];
    }
#pragma unroll
    for (int off = 16; off; off >>= 1)
        s += __shfl_xor_sync(0xffffffffu, s, off);
    const float inv = 1.f / s;
    float* wout = g_w + (size_t)h*II*II + (size_t)i*II;
#pragma unroll
    for (int q = 0; q < 12; q++)
        wout[lane + 32*q] = e[q] * inv;
}

// ---------------------------------------------------------------------------
// K3: per-h GEMM  C[i, n] = sum_j w[h][i][j] * v[s(n)][j][h*32+c(n)]
// Tile 128x128x16, 256 threads, 8x8 micro-tile, f32x2 packed FMA.
// Epilogue: multiply gate, store g_o.  grid = (128, 3, 8)
// ---------------------------------------------------------------------------
#define K3_TK 16
__global__ __launch_bounds__(256, 2) void k3_einsum()
{
    __shared__ __align__(16) float sA[K3_TK][132];   // [k][m]
    __shared__ __align__(16) float sB[K3_TK][128];   // [k][n]
    const int tid = threadIdx.x;
    const int h  = blockIdx.z;
    const int i0 = blockIdx.y * 128;
    const int n0 = blockIdx.x * 128;
    const int s0 = n0 >> 5;              // 4 s-planes per tile
    const int tx = tid & 15;             // n-group
    const int ty = tid >> 4;             // m-group

    // staging indices
    const int ar = tid >> 1;             // A row (m), 0..127
    const int ak = (tid & 1) * 8;        // A k offset: 0 or 8
    const int bk = tid >> 4;             // B k, 0..15
    const int bn_lo = (tid & 15) * 4;    // 0..60
    const int bs_lo = s0 + (bn_lo >> 5);
    const int bc_lo = bn_lo & 31;

    const float* Abase = g_w + (size_t)h*II*II + (size_t)(i0+ar)*II + ak;
    const float* Blo = g_v + (size_t)bs_lo*II*HC + (size_t)h*32 + bc_lo;
    const float* Bhi = g_v + (size_t)(bs_lo+2)*II*HC + (size_t)h*32 + bc_lo;

    unsigned long long acc[8][4];
#pragma unroll
    for (int a = 0; a < 8; a++)
#pragma unroll
        for (int b = 0; b < 4; b++) acc[a][b] = 0ull;

    float4 pa0 = *(const float4*)(Abase);
    float4 pa1 = *(const float4*)(Abase + 4);
    float4 pb0 = *(const float4*)(Blo + (size_t)bk*HC);
    float4 pb1 = *(const float4*)(Bhi + (size_t)bk*HC);

#pragma unroll 1
    for (int j0 = 0; j0 < II; j0 += K3_TK) {
        __syncthreads();
        sA[ak+0][ar] = pa0.x; sA[ak+1][ar] = pa0.y;
        sA[ak+2][ar] = pa0.z; sA[ak+3][ar] = pa0.w;
        sA[ak+4][ar] = pa1.x; sA[ak+5][ar] = pa1.y;
        sA[ak+6][ar] = pa1.z; sA[ak+7][ar] = pa1.w;
        *(float4*)&sB[bk][bn_lo]      = pb0;
        *(float4*)&sB[bk][bn_lo + 64] = pb1;
        __syncthreads();
        if (j0 + K3_TK < II) {
            pa0 = *(const float4*)(Abase + j0 + K3_TK);
            pa1 = *(const float4*)(Abase + j0 + K3_TK + 4);
            pb0 = *(const float4*)(Blo + (size_t)(j0 + K3_TK + bk)*HC);
            pb1 = *(const float4*)(Bhi + (size_t)(j0 + K3_TK + bk)*HC);
        }
#pragma unroll
        for (int k = 0; k < K3_TK; k++) {
            const float4 a0 = *(const float4*)&sA[k][ty*8];
            const float4 a1 = *(const float4*)&sA[k][ty*8 + 4];
            const ulonglong2 bq0 = *(const ulonglong2*)&sB[k][tx*4];
            const ulonglong2 bq1 = *(const ulonglong2*)&sB[k][tx*4 + 64];
            unsigned long long ad;
            ad = pack_dup(a0.x);
            fma2(acc[0][0], ad, bq0.x); fma2(acc[0][1], ad, bq0.y);
            fma2(acc[0][2], ad, bq1.x); fma2(acc[0][3], ad, bq1.y);
            ad = pack_dup(a0.y);
            fma2(acc[1][0], ad, bq0.x); fma2(acc[1][1], ad, bq0.y);
            fma2(acc[1][2], ad, bq1.x); fma2(acc[1][3], ad, bq1.y);
            ad = pack_dup(a0.z);
            fma2(acc[2][0], ad, bq0.x); fma2(acc[2][1], ad, bq0.y);
            fma2(acc[2][2], ad, bq1.x); fma2(acc[2][3], ad, bq1.y);
            ad = pack_dup(a0.w);
            fma2(acc[3][0], ad, bq0.x); fma2(acc[3][1], ad, bq0.y);
            fma2(acc[3][2], ad, bq1.x); fma2(acc[3][3], ad, bq1.y);
            ad = pack_dup(a1.x);
            fma2(acc[4][0], ad, bq0.x); fma2(acc[4][1], ad, bq0.y);
            fma2(acc[4][2], ad, bq1.x); fma2(acc[4][3], ad, bq1.y);
            ad = pack_dup(a1.y);
            fma2(acc[5][0], ad, bq0.x); fma2(acc[5][1], ad, bq0.y);
            fma2(acc[5][2], ad, bq1.x); fma2(acc[5][3], ad, bq1.y);
            ad = pack_dup(a1.z);
            fma2(acc[6][0], ad, bq0.x); fma2(acc[6][1], ad, bq0.y);
            fma2(acc[6][2], ad, bq1.x); fma2(acc[6][3], ad, bq1.y);
            ad = pack_dup(a1.w);
            fma2(acc[7][0], ad, bq0.x); fma2(acc[7][1], ad, bq0.y);
            fma2(acc[7][2], ad, bq1.x); fma2(acc[7][3], ad, bq1.y);
        }
    }

    // epilogue: gate-multiply + store
    const int s_lo = s0 + (tx >> 3);
    const int c_lo = (tx & 7) * 4;
#pragma unroll
    for (int m = 0; m < 8; m++) {
        const int ig = i0 + ty*8 + m;
        {
            const size_t idx = ((size_t)s_lo*II + ig)*HC + h*32 + c_lo;
            const float4 gl = *(const float4*)(g_gate + idx);
            const float2 p0 = unpk(acc[m][0]);
            const float2 p1 = unpk(acc[m][1]);
            *(float4*)(g_o + idx) =
                make_float4(p0.x*gl.x, p0.y*gl.y, p1.x*gl.z, p1.y*gl.w);
        }
        {
            const size_t idx = ((size_t)(s_lo+2)*II + ig)*HC + h*32 + c_lo;
            const float4 gl = *(const float4*)(g_gate + idx);
            const float2 p2 = unpk(acc[m][2]);
            const float2 p3 = unpk(acc[m][3]);
            *(float4*)(g_o + idx) =
                make_float4(p2.x*gl.x, p2.y*gl.y, p3.x*gl.z, p3.y*gl.w);
        }
    }
}

// ---------------------------------------------------------------------------
// K4: out = g_o @ W_out.  M = 196608, K = 256, N = 64.
// Tile 256x64x16, 256 threads, 8x8 micro-tile (m-pairs x dup-B), f32x2.
// grid = 768.
// ---------------------------------------------------------------------------
__global__ __launch_bounds__(256, 2) void k4_out(
    const float* __restrict__ Wout, float* __restrict__ out)
{
    __shared__ __align__(16) float sA[16][260];   // [k][m], m=256
    __shared__ __align__(16) float sBd[16][128];  // [k][2n] duplicated B
    const int tid = threadIdx.x;
    const int r0 = blockIdx.x * 256;
    const int tx = tid & 7;      // n-group: cols tx*4..+3 and +32..+35
    const int ty = tid >> 3;     // m-group: rows ty*8..+7

    const int bk  = tid >> 4;          // B staging k
    const int bn4 = (tid & 15) * 4;    // B staging n base

    const float* Ab = g_o + (size_t)(r0 + tid)*HC;

    unsigned long long acc[4][8];      // [m-pair][n-col]
#pragma unroll
    for (int a = 0; a < 4; a++)
#pragma unroll
        for (int b = 0; b < 8; b++) acc[a][b] = 0ull;

    float4 pa0 = *(const float4*)(Ab);
    float4 pa1 = *(const float4*)(Ab + 4);
    float4 pa2 = *(const float4*)(Ab + 8);
    float4 pa3 = *(const float4*)(Ab + 12);
    float4 pw  = *(const float4*)(Wout + (size_t)bk*CM + bn4);

#pragma unroll 1
    for (int k0 = 0; k0 < HC; k0 += 16) {
        __syncthreads();
        sA[0][tid]  = pa0.x; sA[1][tid]  = pa0.y; sA[2][tid]  = pa0.z; sA[3][tid]  = pa0.w;
        sA[4][tid]  = pa1.x; sA[5][tid]  = pa1.y; sA[6][tid]  = pa1.z; sA[7][tid]  = pa1.w;
        sA[8][tid]  = pa2.x; sA[9][tid]  = pa2.y; sA[10][tid] = pa2.z; sA[11][tid] = pa2.w;
        sA[12][tid] = pa3.x; sA[13][tid] = pa3.y; sA[14][tid] = pa3.z; sA[15][tid] = pa3.w;
        *(float4*)&sBd[bk][bn4*2]     = make_float4(pw.x, pw.x, pw.y, pw.y);
        *(float4*)&sBd[bk][bn4*2 + 4] = make_float4(pw.z, pw.z, pw.w, pw.w);
        __syncthreads();
        if (k0 + 16 < HC) {
            pa0 = *(const float4*)(Ab + k0 + 16);
            pa1 = *(const float4*)(Ab + k0 + 20);
            pa2 = *(const float4*)(Ab + k0 + 24);
            pa3 = *(const float4*)(Ab + k0 + 28);
            pw  = *(const float4*)(Wout + (size_t)(k0 + 16 + bk)*CM + bn4);
        }
#pragma unroll
        for (int k = 0; k < 16; k++) {
            const ulonglong2 av0 = *(const ulonglong2*)&sA[k][ty*8];      // m-pairs 0,1
            const ulonglong2 av1 = *(const ulonglong2*)&sA[k][ty*8 + 4];  // m-pairs 2,3
            const ulonglong2 b0 = *(const ulonglong2*)&sBd[k][tx*8];        // dup n0,n1
            const ulonglong2 b1 = *(const ulonglong2*)&sBd[k][tx*8 + 4];    // dup n2,n3
            const ulonglong2 b2 = *(const ulonglong2*)&sBd[k][tx*8 + 64];   // dup n4,n5
            const ulonglong2 b3 = *(const ulonglong2*)&sBd[k][tx*8 + 68];   // dup n6,n7
            fma2(acc[0][0], av0.x, b0.x); fma2(acc[0][1], av0.x, b0.y);
            fma2(acc[0][2], av0.x, b1.x); fma2(acc[0][3], av0.x, b1.y);
            fma2(acc[0][4], av0.x, b2.x); fma2(acc[0][5], av0.x, b2.y);
            fma2(acc[0][6], av0.x, b3.x); fma2(acc[0][7], av0.x, b3.y);
            fma2(acc[1][0], av0.y, b0.x); fma2(acc[1][1], av0.y, b0.y);
            fma2(acc[1][2], av0.y, b1.x); fma2(acc[1][3], av0.y, b1.y);
            fma2(acc[1][4], av0.y, b2.x); fma2(acc[1][5], av0.y, b2.y);
            fma2(acc[1][6], av0.y, b3.x); fma2(acc[1][7], av0.y, b3.y);
            fma2(acc[2][0], av1.x, b0.x); fma2(acc[2][1], av1.x, b0.y);
            fma2(acc[2][2], av1.x, b1.x); fma2(acc[2][3], av1.x, b1.y);
            fma2(acc[2][4], av1.x, b2.x); fma2(acc[2][5], av1.x, b2.y);
            fma2(acc[2][6], av1.x, b3.x); fma2(acc[2][7], av1.x, b3.y);
            fma2(acc[3][0], av1.y, b0.x); fma2(acc[3][1], av1.y, b0.y);
            fma2(acc[3][2], av1.y, b1.x); fma2(acc[3][3], av1.y, b1.y);
            fma2(acc[3][4], av1.y, b2.x); fma2(acc[3][5], av1.y, b2.y);
            fma2(acc[3][6], av1.y, b3.x); fma2(acc[3][7], av1.y, b3.y);
        }
    }

#pragma unroll
    for (int mp = 0; mp < 4; mp++) {
        const int m_lo = r0 + ty*8 + mp*2;
        const float2 u0 = unpk(acc[mp][0]);
        const float2 u1 = unpk(acc[mp][1]);
        const float2 u2 = unpk(acc[mp][2]);
        const float2 u3 = unpk(acc[mp][3]);
        const float2 u4 = unpk(acc[mp][4]);
        const float2 u5 = unpk(acc[mp][5]);
        const float2 u6 = unpk(acc[mp][6]);
        const float2 u7 = unpk(acc[mp][7]);
        float* o0 = out + (size_t)m_lo*CM + tx*4;
        float* o1 = out + (size_t)(m_lo+1)*CM + tx*4;
        *(float4*)(o0)      = make_float4(u0.x, u1.x, u2.x, u3.x);
        *(float4*)(o0 + 32) = make_float4(u4.x, u5.x, u6.x, u7.x);
        *(float4*)(o1)      = make_float4(u0.y, u1.y, u2.y, u3.y);
        *(float4*)(o1 + 32) = make_float4(u4.y, u5.y, u6.y, u7.y);
    }
}

// ---------------------------------------------------------------------------
extern "C" void kernel_launch(void* const* d_in, const int* in_sizes, int n_in,
                              void* d_out, int out_size)
{
    const float* msa      = (const float*)d_in[0];
    const float* pair     = (const float*)d_in[1];
    const float* ln_msa_g = (const float*)d_in[2];
    const float* ln_msa_b = (const float*)d_in[3];
    const float* ln_pair_g= (const float*)d_in[4];
    const float* ln_pair_b= (const float*)d_in[5];
    const float* W_v      = (const float*)d_in[6];
    const float* W_bias   = (const float*)d_in[7];
    const float* W_gate   = (const float*)d_in[8];
    const float* W_out    = (const float*)d_in[9];
    float* out = (float*)d_out;

    k1_msa<<<2048, 256>>>(msa, ln_msa_g, ln_msa_b, W_v, W_gate);
    k2_bias<<<18432, 256>>>(pair, ln_pair_g, ln_pair_b, W_bias);
    k2_softmax<<<II, 256>>>();
    k3_einsum<<<dim3(128, 3, 8), 256>>>();
    k4_out<<<768, 256>>>(W_out, out);
}

// round 9
// speedup vs baseline: 1.1556x; 1.0583x over previous
#include <cuda_runtime.h>
#include <math.h>

#define SS 512
#define II 384
#define CM 64
#define CZ 128
#define NH 8
#define NC 32
#define HC 256

// Scratch (device globals: allocation-free rule)
__device__ float g_v[SS*II*HC];      // v[s][j][h*32+c]
__device__ float g_gate[SS*II*HC];   // sigmoid(msa_n @ W_gate)
__device__ float g_bias[II*II*NH];   // bias[i][j][h] pre-softmax
__device__ float g_w[NH*II*II];      // softmaxed weights, [h][i][j]
__device__ float g_o[SS*II*HC];      // gate * weighted average

// ---------------------------------------------------------------------------
// f32x2 packed-math helpers (Blackwell dual fp32 path; PTX-only)
// ---------------------------------------------------------------------------
__device__ __forceinline__ void fma2(unsigned long long& d,
                                     unsigned long long a,
                                     unsigned long long b)
{
    asm("fma.rn.f32x2 %0, %1, %2, %0;" : "+l"(d) : "l"(a), "l"(b));
}
__device__ __forceinline__ unsigned long long pack_dup(float x)
{
    unsigned long long r;
    asm("mov.b64 %0, {%1, %1};" : "=l"(r) : "r"(__float_as_uint(x)));
    return r;
}
__device__ __forceinline__ unsigned long long pack2(float lo, float hi)
{
    unsigned long long r;
    asm("mov.b64 %0, {%1, %2};" : "=l"(r)
        : "r"(__float_as_uint(lo)), "r"(__float_as_uint(hi)));
    return r;
}
__device__ __forceinline__ float2 unpk(unsigned long long v)
{
    float2 r;
    asm("mov.b64 {%0, %1}, %2;" : "=f"(r.x), "=f"(r.y) : "l"(v));
    return r;
}
__device__ __forceinline__ void add2(unsigned long long& d, unsigned long long a)
{
    asm("add.rn.f32x2 %0, %0, %1;" : "+l"(d) : "l"(a));
}

// ---------------------------------------------------------------------------
// K1: msa LN + V + gate.  rows = S*I = 196608.  Block: 256 thr, 96 rows.
// Packed weights w2[c] = (Wv[c][tid], Wg[c][tid]).  Double-buffered LN rows:
// one __syncthreads per 8-row batch; LN of batch i+1 overlaps GEMV of batch i.
// ---------------------------------------------------------------------------
__global__ __launch_bounds__(256) void k1_msa(
    const float* __restrict__ msa,
    const float* __restrict__ lng, const float* __restrict__ lnb,
    const float* __restrict__ Wv,  const float* __restrict__ Wg)
{
    __shared__ __align__(16) float2 sy2[2][8][CM];   // duplicated LN rows
    const int tid = threadIdx.x;
    const int warp = tid >> 5, lane = tid & 31;

    unsigned long long w2[CM];
#pragma unroll
    for (int c = 0; c < CM; c++)
        w2[c] = pack2(Wv[c*HC + tid], Wg[c*HC + tid]);

    const float g0 = lng[lane*2], g1 = lng[lane*2+1];
    const float b0 = lnb[lane*2], b1 = lnb[lane*2+1];

    const int base = blockIdx.x * 96;

    // prologue: LN batch 0 into buf 0
    {
        const float2 x = ((const float2*)(msa + (size_t)(base + warp)*CM))[lane];
        float s1 = x.x + x.y;
        float s2 = x.x*x.x + x.y*x.y;
#pragma unroll
        for (int off = 16; off; off >>= 1) {
            s1 += __shfl_xor_sync(0xffffffffu, s1, off);
            s2 += __shfl_xor_sync(0xffffffffu, s2, off);
        }
        const float mu  = s1 * (1.f/64.f);
        const float var = s2 * (1.f/64.f) - mu*mu;
        const float rs  = rsqrtf(var + 1e-5f);
        const float y0 = (x.x - mu)*rs*g0 + b0;
        const float y1 = (x.y - mu)*rs*g1 + b1;
        sy2[0][warp][lane*2]   = make_float2(y0, y0);
        sy2[0][warp][lane*2+1] = make_float2(y1, y1);
    }
    __syncthreads();

#pragma unroll 1
    for (int it = 0; it < 12; it++) {
        const int b = it & 1;
        float2 x;
        const bool more = (it + 1 < 12);
        if (more)
            x = ((const float2*)(msa + (size_t)(base + (it+1)*8 + warp)*CM))[lane];

        // GEMV on buffer b (8 rows)
#pragma unroll 1
        for (int r = 0; r < 8; r++) {
            unsigned long long a0 = 0ull, a1 = 0ull, a2 = 0ull, a3 = 0ull;
#pragma unroll
            for (int c = 0; c < CM; c += 4) {
                const ulonglong2 q0 = *(const ulonglong2*)&sy2[b][r][c];
                const ulonglong2 q1 = *(const ulonglong2*)&sy2[b][r][c+2];
                fma2(a0, q0.x, w2[c]);
                fma2(a1, q0.y, w2[c+1]);
                fma2(a2, q1.x, w2[c+2]);
                fma2(a3, q1.y, w2[c+3]);
            }
            add2(a0, a1); add2(a2, a3); add2(a0, a2);
            const float2 res = unpk(a0);
            const size_t orow = (size_t)(base + it*8 + r) * HC;
            g_v[orow + tid]    = res.x;
            g_gate[orow + tid] = 1.f / (1.f + expf(-res.y));
        }

        if (more) {
            float s1 = x.x + x.y;
            float s2 = x.x*x.x + x.y*x.y;
#pragma unroll
            for (int off = 16; off; off >>= 1) {
                s1 += __shfl_xor_sync(0xffffffffu, s1, off);
                s2 += __shfl_xor_sync(0xffffffffu, s2, off);
            }
            const float mu  = s1 * (1.f/64.f);
            const float var = s2 * (1.f/64.f) - mu*mu;
            const float rs  = rsqrtf(var + 1e-5f);
            const float y0 = (x.x - mu)*rs*g0 + b0;
            const float y1 = (x.y - mu)*rs*g1 + b1;
            sy2[b^1][warp][lane*2]   = make_float2(y0, y0);
            sy2[b^1][warp][lane*2+1] = make_float2(y1, y1);
        }
        __syncthreads();
    }
}

// ---------------------------------------------------------------------------
// K2a: pair LN + bias matvec.  rows = I*I = 147456, 1 warp per row.
// ---------------------------------------------------------------------------
__global__ __launch_bounds__(256) void k2_bias(
    const float* __restrict__ pair,
    const float* __restrict__ lng, const float* __restrict__ lnb,
    const float* __restrict__ Wb)
{
    const int tid = threadIdx.x, warp = tid >> 5, lane = tid & 31;
    const int row = blockIdx.x * 8 + warp;

    const float4 x = ((const float4*)(pair + (size_t)row*CZ))[lane];
    float s1 = x.x + x.y + x.z + x.w;
    float s2 = x.x*x.x + x.y*x.y + x.z*x.z + x.w*x.w;
#pragma unroll
    for (int off = 16; off; off >>= 1) {
        s1 += __shfl_xor_sync(0xffffffffu, s1, off);
        s2 += __shfl_xor_sync(0xffffffffu, s2, off);
    }
    const float mu  = s1 * (1.f/128.f);
    const float var = s2 * (1.f/128.f) - mu*mu;
    const float rs  = rsqrtf(var + 1e-5f);

    const float4 gg = ((const float4*)lng)[lane];
    const float4 bb = ((const float4*)lnb)[lane];
    float y[4];
    y[0] = (x.x - mu)*rs*gg.x + bb.x;
    y[1] = (x.y - mu)*rs*gg.y + bb.y;
    y[2] = (x.z - mu)*rs*gg.z + bb.z;
    y[3] = (x.w - mu)*rs*gg.w + bb.w;

    float acc0=0,acc1=0,acc2=0,acc3=0,acc4=0,acc5=0,acc6=0,acc7=0;
#pragma unroll
    for (int q = 0; q < 4; q++) {
        const float yq = y[q];
        const float4* wrow = (const float4*)(Wb + (size_t)(4*lane+q)*NH);
        const float4 w0 = wrow[0], w1 = wrow[1];
        acc0 = fmaf(yq, w0.x, acc0); acc1 = fmaf(yq, w0.y, acc1);
        acc2 = fmaf(yq, w0.z, acc2); acc3 = fmaf(yq, w0.w, acc3);
        acc4 = fmaf(yq, w1.x, acc4); acc5 = fmaf(yq, w1.y, acc5);
        acc6 = fmaf(yq, w1.z, acc6); acc7 = fmaf(yq, w1.w, acc7);
    }
#pragma unroll
    for (int off = 16; off; off >>= 1) {
        acc0 += __shfl_xor_sync(0xffffffffu, acc0, off);
        acc1 += __shfl_xor_sync(0xffffffffu, acc1, off);
        acc2 += __shfl_xor_sync(0xffffffffu, acc2, off);
        acc3 += __shfl_xor_sync(0xffffffffu, acc3, off);
        acc4 += __shfl_xor_sync(0xffffffffu, acc4, off);
        acc5 += __shfl_xor_sync(0xffffffffu, acc5, off);
        acc6 += __shfl_xor_sync(0xffffffffu, acc6, off);
        acc7 += __shfl_xor_sync(0xffffffffu, acc7, off);
    }
    if (lane == 0) {
        float4* op = (float4*)(g_bias + (size_t)row*NH);
        op[0] = make_float4(acc0, acc1, acc2, acc3);
        op[1] = make_float4(acc4, acc5, acc6, acc7);
    }
}

// ---------------------------------------------------------------------------
// K2b: softmax over j per (i,h); write transposed layout g_w[h][i][j].
// ---------------------------------------------------------------------------
__global__ __launch_bounds__(256) void k2_softmax()
{
    __shared__ float sb[II][NH+1];
    const int tid = threadIdx.x;
    const int i = blockIdx.x;
    for (int idx = tid; idx < II*NH; idx += 256)
        sb[idx/NH][idx%NH] = g_bias[(size_t)i*II*NH + idx];
    __syncthreads();

    const int h = tid >> 5, lane = tid & 31;
    float v[12];
    float m = -1e30f;
#pragma unroll
    for (int q = 0; q < 12; q++) {
        v[q] = sb[lane + 32*q][h];
        m = fmaxf(m, v[q]);
    }
#pragma unroll
    for (int off = 16; off; off >>= 1)
        m = fmaxf(m, __shfl_xor_sync(0xffffffffu, m, off));
    float s = 0.f;
    float e[12];
#pragma unroll
    for (int q = 0; q < 12; q++) {
        e[q] = expf(v[q] - m);
        s += e[q];
    }
#pragma unroll
    for (int off = 16; off; off >>= 1)
        s += __shfl_xor_sync(0xffffffffu, s, off);
    const float inv = 1.f / s;
    float* wout = g_w + (size_t)h*II*II + (size_t)i*II;
#pragma unroll
    for (int q = 0; q < 12; q++)
        wout[lane + 32*q] = e[q] * inv;
}

// ---------------------------------------------------------------------------
// K3: per-h GEMM  C[i, n] = sum_j w[h][i][j] * v[s(n)][j][h*32+c(n)]
// Tile 128x128x16, 256 threads, 8x8 micro-tile, f32x2 packed FMA.
// Double-buffered smem: ONE __syncthreads per k-tile.
// Epilogue: multiply gate, store g_o.  grid = (128, 3, 8)
// ---------------------------------------------------------------------------
#define K3_TK 16
__global__ __launch_bounds__(256, 2) void k3_einsum()
{
    __shared__ __align__(16) float sA[2][K3_TK][132];   // [buf][k][m]
    __shared__ __align__(16) float sB[2][K3_TK][128];   // [buf][k][n]
    const int tid = threadIdx.x;
    const int h  = blockIdx.z;
    const int i0 = blockIdx.y * 128;
    const int n0 = blockIdx.x * 128;
    const int s0 = n0 >> 5;              // 4 s-planes per tile
    const int tx = tid & 15;             // n-group
    const int ty = tid >> 4;             // m-group

    // staging indices
    const int ar = tid >> 1;             // A row (m), 0..127
    const int ak = (tid & 1) * 8;        // A k offset: 0 or 8
    const int bk = tid >> 4;             // B k, 0..15
    const int bn_lo = (tid & 15) * 4;    // 0..60
    const int bs_lo = s0 + (bn_lo >> 5);
    const int bc_lo = bn_lo & 31;

    const float* Abase = g_w + (size_t)h*II*II + (size_t)(i0+ar)*II + ak;
    const float* Blo = g_v + (size_t)bs_lo*II*HC + (size_t)h*32 + bc_lo;
    const float* Bhi = g_v + (size_t)(bs_lo+2)*II*HC + (size_t)h*32 + bc_lo;

    unsigned long long acc[8][4];
#pragma unroll
    for (int a = 0; a < 8; a++)
#pragma unroll
        for (int b = 0; b < 4; b++) acc[a][b] = 0ull;

    // prologue: fetch + stage tile 0 into buf 0
    {
        const float4 pa0 = *(const float4*)(Abase);
        const float4 pa1 = *(const float4*)(Abase + 4);
        const float4 pb0 = *(const float4*)(Blo + (size_t)bk*HC);
        const float4 pb1 = *(const float4*)(Bhi + (size_t)bk*HC);
        sA[0][ak+0][ar] = pa0.x; sA[0][ak+1][ar] = pa0.y;
        sA[0][ak+2][ar] = pa0.z; sA[0][ak+3][ar] = pa0.w;
        sA[0][ak+4][ar] = pa1.x; sA[0][ak+5][ar] = pa1.y;
        sA[0][ak+6][ar] = pa1.z; sA[0][ak+7][ar] = pa1.w;
        *(float4*)&sB[0][bk][bn_lo]      = pb0;
        *(float4*)&sB[0][bk][bn_lo + 64] = pb1;
    }
    __syncthreads();

    int buf = 0;
#pragma unroll 1
    for (int j0 = 0; j0 < II; j0 += K3_TK) {
        const bool more = (j0 + K3_TK < II);
        float4 pa0, pa1, pb0, pb1;
        if (more) {
            pa0 = *(const float4*)(Abase + j0 + K3_TK);
            pa1 = *(const float4*)(Abase + j0 + K3_TK + 4);
            pb0 = *(const float4*)(Blo + (size_t)(j0 + K3_TK + bk)*HC);
            pb1 = *(const float4*)(Bhi + (size_t)(j0 + K3_TK + bk)*HC);
        }
#pragma unroll
        for (int k = 0; k < K3_TK; k++) {
            const float4 a0 = *(const float4*)&sA[buf][k][ty*8];
            const float4 a1 = *(const float4*)&sA[buf][k][ty*8 + 4];
            const ulonglong2 bq0 = *(const ulonglong2*)&sB[buf][k][tx*4];
            const ulonglong2 bq1 = *(const ulonglong2*)&sB[buf][k][tx*4 + 64];
            unsigned long long ad;
            ad = pack_dup(a0.x);
            fma2(acc[0][0], ad, bq0.x); fma2(acc[0][1], ad, bq0.y);
            fma2(acc[0][2], ad, bq1.x); fma2(acc[0][3], ad, bq1.y);
            ad = pack_dup(a0.y);
            fma2(acc[1][0], ad, bq0.x); fma2(acc[1][1], ad, bq0.y);
            fma2(acc[1][2], ad, bq1.x); fma2(acc[1][3], ad, bq1.y);
            ad = pack_dup(a0.z);
            fma2(acc[2][0], ad, bq0.x); fma2(acc[2][1], ad, bq0.y);
            fma2(acc[2][2], ad, bq1.x); fma2(acc[2][3], ad, bq1.y);
            ad = pack_dup(a0.w);
            fma2(acc[3][0], ad, bq0.x); fma2(acc[3][1], ad, bq0.y);
            fma2(acc[3][2], ad, bq1.x); fma2(acc[3][3], ad, bq1.y);
            ad = pack_dup(a1.x);
            fma2(acc[4][0], ad, bq0.x); fma2(acc[4][1], ad, bq0.y);
            fma2(acc[4][2], ad, bq1.x); fma2(acc[4][3], ad, bq1.y);
            ad = pack_dup(a1.y);
            fma2(acc[5][0], ad, bq0.x); fma2(acc[5][1], ad, bq0.y);
            fma2(acc[5][2], ad, bq1.x); fma2(acc[5][3], ad, bq1.y);
            ad = pack_dup(a1.z);
            fma2(acc[6][0], ad, bq0.x); fma2(acc[6][1], ad, bq0.y);
            fma2(acc[6][2], ad, bq1.x); fma2(acc[6][3], ad, bq1.y);
            ad = pack_dup(a1.w);
            fma2(acc[7][0], ad, bq0.x); fma2(acc[7][1], ad, bq0.y);
            fma2(acc[7][2], ad, bq1.x); fma2(acc[7][3], ad, bq1.y);
        }
        if (more) {
            const int nb = buf ^ 1;
            sA[nb][ak+0][ar] = pa0.x; sA[nb][ak+1][ar] = pa0.y;
            sA[nb][ak+2][ar] = pa0.z; sA[nb][ak+3][ar] = pa0.w;
            sA[nb][ak+4][ar] = pa1.x; sA[nb][ak+5][ar] = pa1.y;
            sA[nb][ak+6][ar] = pa1.z; sA[nb][ak+7][ar] = pa1.w;
            *(float4*)&sB[nb][bk][bn_lo]      = pb0;
            *(float4*)&sB[nb][bk][bn_lo + 64] = pb1;
        }
        __syncthreads();
        buf ^= 1;
    }

    // epilogue: gate-multiply + store
    const int s_lo = s0 + (tx >> 3);
    const int c_lo = (tx & 7) * 4;
#pragma unroll
    for (int m = 0; m < 8; m++) {
        const int ig = i0 + ty*8 + m;
        {
            const size_t idx = ((size_t)s_lo*II + ig)*HC + h*32 + c_lo;
            const float4 gl = *(const float4*)(g_gate + idx);
            const float2 p0 = unpk(acc[m][0]);
            const float2 p1 = unpk(acc[m][1]);
            *(float4*)(g_o + idx) =
                make_float4(p0.x*gl.x, p0.y*gl.y, p1.x*gl.z, p1.y*gl.w);
        }
        {
            const size_t idx = ((size_t)(s_lo+2)*II + ig)*HC + h*32 + c_lo;
            const float4 gl = *(const float4*)(g_gate + idx);
            const float2 p2 = unpk(acc[m][2]);
            const float2 p3 = unpk(acc[m][3]);
            *(float4*)(g_o + idx) =
                make_float4(p2.x*gl.x, p2.y*gl.y, p3.x*gl.z, p3.y*gl.w);
        }
    }
}

// ---------------------------------------------------------------------------
// K4: out = g_o @ W_out.  M = 196608, K = 256, N = 64.
// Tile 256x64x16, 256 threads, 8x8 micro-tile (m-pairs x dup-B), f32x2.
// Double-buffered smem: ONE __syncthreads per k-tile.  grid = 768.
// ---------------------------------------------------------------------------
__global__ __launch_bounds__(256, 2) void k4_out(
    const float* __restrict__ Wout, float* __restrict__ out)
{
    __shared__ __align__(16) float sA[2][16][260];   // [buf][k][m], m=256
    __shared__ __align__(16) float sBd[2][16][128];  // [buf][k][2n] dup B
    const int tid = threadIdx.x;
    const int r0 = blockIdx.x * 256;
    const int tx = tid & 7;      // n-group: cols tx*4..+3 and +32..+35
    const int ty = tid >> 3;     // m-group: rows ty*8..+7

    const int bk  = tid >> 4;          // B staging k
    const int bn4 = (tid & 15) * 4;    // B staging n base

    const float* Ab = g_o + (size_t)(r0 + tid)*HC;

    unsigned long long acc[4][8];      // [m-pair][n-col]
#pragma unroll
    for (int a = 0; a < 4; a++)
#pragma unroll
        for (int b = 0; b < 8; b++) acc[a][b] = 0ull;

    // prologue: fetch + stage tile 0 into buf 0
    {
        const float4 pa0 = *(const float4*)(Ab);
        const float4 pa1 = *(const float4*)(Ab + 4);
        const float4 pa2 = *(const float4*)(Ab + 8);
        const float4 pa3 = *(const float4*)(Ab + 12);
        const float4 pw  = *(const float4*)(Wout + (size_t)bk*CM + bn4);
        sA[0][0][tid]  = pa0.x; sA[0][1][tid]  = pa0.y; sA[0][2][tid]  = pa0.z; sA[0][3][tid]  = pa0.w;
        sA[0][4][tid]  = pa1.x; sA[0][5][tid]  = pa1.y; sA[0][6][tid]  = pa1.z; sA[0][7][tid]  = pa1.w;
        sA[0][8][tid]  = pa2.x; sA[0][9][tid]  = pa2.y; sA[0][10][tid] = pa2.z; sA[0][11][tid] = pa2.w;
        sA[0][12][tid] = pa3.x; sA[0][13][tid] = pa3.y; sA[0][14][tid] = pa3.z; sA[0][15][tid] = pa3.w;
        *(float4*)&sBd[0][bk][bn4*2]     = make_float4(pw.x, pw.x, pw.y, pw.y);
        *(float4*)&sBd[0][bk][bn4*2 + 4] = make_float4(pw.z, pw.z, pw.w, pw.w);
    }
    __syncthreads();

    int buf = 0;
#pragma unroll 1
    for (int k0 = 0; k0 < HC; k0 += 16) {
        const bool more = (k0 + 16 < HC);
        float4 pa0, pa1, pa2, pa3, pw;
        if (more) {
            pa0 = *(const float4*)(Ab + k0 + 16);
            pa1 = *(const float4*)(Ab + k0 + 20);
            pa2 = *(const float4*)(Ab + k0 + 24);
            pa3 = *(const float4*)(Ab + k0 + 28);
            pw  = *(const float4*)(Wout + (size_t)(k0 + 16 + bk)*CM + bn4);
        }
#pragma unroll
        for (int k = 0; k < 16; k++) {
            const ulonglong2 av0 = *(const ulonglong2*)&sA[buf][k][ty*8];      // m-pairs 0,1
            const ulonglong2 av1 = *(const ulonglong2*)&sA[buf][k][ty*8 + 4];  // m-pairs 2,3
            const ulonglong2 b0 = *(const ulonglong2*)&sBd[buf][k][tx*8];        // dup n0,n1
            const ulonglong2 b1 = *(const ulonglong2*)&sBd[buf][k][tx*8 + 4];    // dup n2,n3
            const ulonglong2 b2 = *(const ulonglong2*)&sBd[buf][k][tx*8 + 64];   // dup n4,n5
            const ulonglong2 b3 = *(const ulonglong2*)&sBd[buf][k][tx*8 + 68];   // dup n6,n7
            fma2(acc[0][0], av0.x, b0.x); fma2(acc[0][1], av0.x, b0.y);
            fma2(acc[0][2], av0.x, b1.x); fma2(acc[0][3], av0.x, b1.y);
            fma2(acc[0][4], av0.x, b2.x); fma2(acc[0][5], av0.x, b2.y);
            fma2(acc[0][6], av0.x, b3.x); fma2(acc[0][7], av0.x, b3.y);
            fma2(acc[1][0], av0.y, b0.x); fma2(acc[1][1], av0.y, b0.y);
            fma2(acc[1][2], av0.y, b1.x); fma2(acc[1][3], av0.y, b1.y);
            fma2(acc[1][4], av0.y, b2.x); fma2(acc[1][5], av0.y, b2.y);
            fma2(acc[1][6], av0.y, b3.x); fma2(acc[1][7], av0.y, b3.y);
            fma2(acc[2][0], av1.x, b0.x); fma2(acc[2][1], av1.x, b0.y);
            fma2(acc[2][2], av1.x, b1.x); fma2(acc[2][3], av1.x, b1.y);
            fma2(acc[2][4], av1.x, b2.x); fma2(acc[2][5], av1.x, b2.y);
            fma2(acc[2][6], av1.x, b3.x); fma2(acc[2][7], av1.x, b3.y);
            fma2(acc[3][0], av1.y, b0.x); fma2(acc[3][1], av1.y, b0.y);
            fma2(acc[3][2], av1.y, b1.x); fma2(acc[3][3], av1.y, b1.y);
            fma2(acc[3][4], av1.y, b2.x); fma2(acc[3][5], av1.y, b2.y);
            fma2(acc[3][6], av1.y, b3.x); fma2(acc[3][7], av1.y, b3.y);
        }
        if (more) {
            const int nb = buf ^ 1;
            sA[nb][0][tid]  = pa0.x; sA[nb][1][tid]  = pa0.y; sA[nb][2][tid]  = pa0.z; sA[nb][3][tid]  = pa0.w;
            sA[nb][4][tid]  = pa1.x; sA[nb][5][tid]  = pa1.y; sA[nb][6][tid]  = pa1.z; sA[nb][7][tid]  = pa1.w;
            sA[nb][8][tid]  = pa2.x; sA[nb][9][tid]  = pa2.y; sA[nb][10][tid] = pa2.z; sA[nb][11][tid] = pa2.w;
            sA[nb][12][tid] = pa3.x; sA[nb][13][tid] = pa3.y; sA[nb][14][tid] = pa3.z; sA[nb][15][tid] = pa3.w;
            *(float4*)&sBd[nb][bk][bn4*2]     = make_float4(pw.x, pw.x, pw.y, pw.y);
            *(float4*)&sBd[nb][bk][bn4*2 + 4] = make_float4(pw.z, pw.z, pw.w, pw.w);
        }
        __syncthreads();
        buf ^= 1;
    }

#pragma unroll
    for (int mp = 0; mp < 4; mp++) {
        const int m_lo = r0 + ty*8 + mp*2;
        const float2 u0 = unpk(acc[mp][0]);
        const float2 u1 = unpk(acc[mp][1]);
        const float2 u2 = unpk(acc[mp][2]);
        const float2 u3 = unpk(acc[mp][3]);
        const float2 u4 = unpk(acc[mp][4]);
        const float2 u5 = unpk(acc[mp][5]);
        const float2 u6 = unpk(acc[mp][6]);
        const float2 u7 = unpk(acc[mp][7]);
        float* o0 = out + (size_t)m_lo*CM + tx*4;
        float* o1 = out + (size_t)(m_lo+1)*CM + tx*4;
        *(float4*)(o0)      = make_float4(u0.x, u1.x, u2.x, u3.x);
        *(float4*)(o0 + 32) = make_float4(u4.x, u5.x, u6.x, u7.x);
        *(float4*)(o1)      = make_float4(u0.y, u1.y, u2.y, u3.y);
        *(float4*)(o1 + 32) = make_float4(u4.y, u5.y, u6.y, u7.y);
    }
}

// ---------------------------------------------------------------------------
extern "C" void kernel_launch(void* const* d_in, const int* in_sizes, int n_in,
                              void* d_out, int out_size)
{
    const float* msa      = (const float*)d_in[0];
    const float* pair     = (const float*)d_in[1];
    const float* ln_msa_g = (const float*)d_in[2];
    const float* ln_msa_b = (const float*)d_in[3];
    const float* ln_pair_g= (const float*)d_in[4];
    const float* ln_pair_b= (const float*)d_in[5];
    const float* W_v      = (const float*)d_in[6];
    const float* W_bias   = (const float*)d_in[7];
    const float* W_gate   = (const float*)d_in[8];
    const float* W_out    = (const float*)d_in[9];
    float* out = (float*)d_out;

    k1_msa<<<2048, 256>>>(msa, ln_msa_g, ln_msa_b, W_v, W_gate);
    k2_bias<<<18432, 256>>>(pair, ln_pair_g, ln_pair_b, W_bias);
    k2_softmax<<<II, 256>>>();
    k3_einsum<<<dim3(128, 3, 8), 256>>>();
    k4_out<<<768, 256>>>(W_out, out);
}

// round 14
// speedup vs baseline: 1.5594x; 1.3495x over previous
#include <cuda_runtime.h>
#include <cuda_fp16.h>
#include <stdint.h>
#include <math.h>

#define SS 512
#define II 384
#define CM 64
#define CZ 128
#define NH 8
#define NC 32
#define HC 256

// Scratch (device globals: allocation-free rule)
__device__ __half g_vh[(size_t)NH*SS*II*NC];  // v fp16, [h][s][j][c]
__device__ __half g_wh[(size_t)NH*II*II];     // softmax weights fp16, [h][i][j]
__device__ float g_gate[(size_t)SS*II*HC];    // sigmoid(msa_n @ W_gate)
__device__ float g_bias[(size_t)II*II*NH];    // bias[i][j][h] pre-softmax
__device__ float g_o[(size_t)SS*II*HC];       // gate * weighted average

// ---------------------------------------------------------------------------
// f32x2 packed-math helpers (Blackwell dual fp32 path; PTX-only)
// ---------------------------------------------------------------------------
__device__ __forceinline__ void fma2(unsigned long long& d,
                                     unsigned long long a,
                                     unsigned long long b)
{
    asm("fma.rn.f32x2 %0, %1, %2, %0;" : "+l"(d) : "l"(a), "l"(b));
}
__device__ __forceinline__ unsigned long long pack2(float lo, float hi)
{
    unsigned long long r;
    asm("mov.b64 %0, {%1, %2};" : "=l"(r)
        : "r"(__float_as_uint(lo)), "r"(__float_as_uint(hi)));
    return r;
}
__device__ __forceinline__ float2 unpk(unsigned long long v)
{
    float2 r;
    asm("mov.b64 {%0, %1}, %2;" : "=f"(r.x), "=f"(r.y) : "l"(v));
    return r;
}
__device__ __forceinline__ void add2(unsigned long long& d, unsigned long long a)
{
    asm("add.rn.f32x2 %0, %0, %1;" : "+l"(d) : "l"(a));
}

// ---------------------------------------------------------------------------
// mma.sync / ldmatrix helpers (baseline PTX, valid on compute_103)
// ---------------------------------------------------------------------------
__device__ __forceinline__ unsigned smem_u32(const void* p)
{
    unsigned a;
    asm("{ .reg .u64 t; cvta.to.shared.u64 t, %1; cvt.u32.u64 %0, t; }"
        : "=r"(a) : "l"(p));
    return a;
}
__device__ __forceinline__ void ldsm_x4(unsigned& r0, unsigned& r1,
                                        unsigned& r2, unsigned& r3, unsigned a)
{
    asm volatile("ldmatrix.sync.aligned.m8n8.x4.shared.b16 {%0,%1,%2,%3}, [%4];"
                 : "=r"(r0), "=r"(r1), "=r"(r2), "=r"(r3) : "r"(a));
}
__device__ __forceinline__ void ldsm_x4t(unsigned& r0, unsigned& r1,
                                         unsigned& r2, unsigned& r3, unsigned a)
{
    asm volatile("ldmatrix.sync.aligned.m8n8.x4.trans.shared.b16 {%0,%1,%2,%3}, [%4];"
                 : "=r"(r0), "=r"(r1), "=r"(r2), "=r"(r3) : "r"(a));
}
__device__ __forceinline__ void mma16816(float* c, const unsigned* a,
                                         unsigned b0, unsigned b1)
{
    asm volatile(
        "mma.sync.aligned.m16n8k16.row.col.f32.f16.f16.f32 "
        "{%0,%1,%2,%3}, {%4,%5,%6,%7}, {%8,%9}, {%0,%1,%2,%3};"
        : "+f"(c[0]), "+f"(c[1]), "+f"(c[2]), "+f"(c[3])
        : "r"(a[0]), "r"(a[1]), "r"(a[2]), "r"(a[3]), "r"(b0), "r"(b1));
}

// ---------------------------------------------------------------------------
// K1: msa LN + V + gate.  rows = S*I = 196608.  Block: 256 thr, 96 rows.
// Writes g_vh fp16 in [h][s][j][c] layout (warp = h -> coalesced 64B) and
// g_gate f32 in [s][i][hc].
// ---------------------------------------------------------------------------
__global__ __launch_bounds__(256) void k1_msa(
    const float* __restrict__ msa,
    const float* __restrict__ lng, const float* __restrict__ lnb,
    const float* __restrict__ Wv,  const float* __restrict__ Wg)
{
    __shared__ __align__(16) float2 sy2[2][8][CM];   // duplicated LN rows
    const int tid = threadIdx.x;
    const int warp = tid >> 5, lane = tid & 31;

    unsigned long long w2[CM];
#pragma unroll
    for (int c = 0; c < CM; c++)
        w2[c] = pack2(Wv[c*HC + tid], Wg[c*HC + tid]);

    const float g0 = lng[lane*2], g1 = lng[lane*2+1];
    const float b0 = lnb[lane*2], b1 = lnb[lane*2+1];

    const int base = blockIdx.x * 96;

    // prologue: LN batch 0 into buf 0
    {
        const float2 x = ((const float2*)(msa + (size_t)(base + warp)*CM))[lane];
        float s1 = x.x + x.y;
        float s2 = x.x*x.x + x.y*x.y;
#pragma unroll
        for (int off = 16; off; off >>= 1) {
            s1 += __shfl_xor_sync(0xffffffffu, s1, off);
            s2 += __shfl_xor_sync(0xffffffffu, s2, off);
        }
        const float mu  = s1 * (1.f/64.f);
        const float var = s2 * (1.f/64.f) - mu*mu;
        const float rs  = rsqrtf(var + 1e-5f);
        const float y0 = (x.x - mu)*rs*g0 + b0;
        const float y1 = (x.y - mu)*rs*g1 + b1;
        sy2[0][warp][lane*2]   = make_float2(y0, y0);
        sy2[0][warp][lane*2+1] = make_float2(y1, y1);
    }
    __syncthreads();

#pragma unroll 1
    for (int it = 0; it < 12; it++) {
        const int b = it & 1;
        float2 x;
        const bool more = (it + 1 < 12);
        if (more)
            x = ((const float2*)(msa + (size_t)(base + (it+1)*8 + warp)*CM))[lane];

        // GEMV on buffer b (8 rows)
#pragma unroll 1
        for (int r = 0; r < 8; r++) {
            unsigned long long a0 = 0ull, a1 = 0ull, a2 = 0ull, a3 = 0ull;
#pragma unroll
            for (int c = 0; c < CM; c += 4) {
                const ulonglong2 q0 = *(const ulonglong2*)&sy2[b][r][c];
                const ulonglong2 q1 = *(const ulonglong2*)&sy2[b][r][c+2];
                fma2(a0, q0.x, w2[c]);
                fma2(a1, q0.y, w2[c+1]);
                fma2(a2, q1.x, w2[c+2]);
                fma2(a3, q1.y, w2[c+3]);
            }
            add2(a0, a1); add2(a2, a3); add2(a0, a2);
            const float2 res = unpk(a0);
            const int rg = base + it*8 + r;
            const int s = rg / II;
            const int ii = rg - s*II;
            g_vh[(((size_t)warp*SS + s)*II + ii)*NC + lane] = __float2half_rn(res.x);
            g_gate[(size_t)rg*HC + tid] = 1.f / (1.f + expf(-res.y));
        }

        if (more) {
            float s1 = x.x + x.y;
            float s2 = x.x*x.x + x.y*x.y;
#pragma unroll
            for (int off = 16; off; off >>= 1) {
                s1 += __shfl_xor_sync(0xffffffffu, s1, off);
                s2 += __shfl_xor_sync(0xffffffffu, s2, off);
            }
            const float mu  = s1 * (1.f/64.f);
            const float var = s2 * (1.f/64.f) - mu*mu;
            const float rs  = rsqrtf(var + 1e-5f);
            const float y0 = (x.x - mu)*rs*g0 + b0;
            const float y1 = (x.y - mu)*rs*g1 + b1;
            sy2[b^1][warp][lane*2]   = make_float2(y0, y0);
            sy2[b^1][warp][lane*2+1] = make_float2(y1, y1);
        }
        __syncthreads();
    }
}

// ---------------------------------------------------------------------------
// K2a: pair LN + bias matvec.  rows = I*I = 147456, 1 warp per row.
// ---------------------------------------------------------------------------
__global__ __launch_bounds__(256) void k2_bias(
    const float* __restrict__ pair,
    const float* __restrict__ lng, const float* __restrict__ lnb,
    const float* __restrict__ Wb)
{
    const int tid = threadIdx.x, warp = tid >> 5, lane = tid & 31;
    const int row = blockIdx.x * 8 + warp;

    const float4 x = ((const float4*)(pair + (size_t)row*CZ))[lane];
    float s1 = x.x + x.y + x.z + x.w;
    float s2 = x.x*x.x + x.y*x.y + x.z*x.z + x.w*x.w;
#pragma unroll
    for (int off = 16; off; off >>= 1) {
        s1 += __shfl_xor_sync(0xffffffffu, s1, off);
        s2 += __shfl_xor_sync(0xffffffffu, s2, off);
    }
    const float mu  = s1 * (1.f/128.f);
    const float var = s2 * (1.f/128.f) - mu*mu;
    const float rs  = rsqrtf(var + 1e-5f);

    const float4 gg = ((const float4*)lng)[lane];
    const float4 bb = ((const float4*)lnb)[lane];
    float y[4];
    y[0] = (x.x - mu)*rs*gg.x + bb.x;
    y[1] = (x.y - mu)*rs*gg.y + bb.y;
    y[2] = (x.z - mu)*rs*gg.z + bb.z;
    y[3] = (x.w - mu)*rs*gg.w + bb.w;

    float acc0=0,acc1=0,acc2=0,acc3=0,acc4=0,acc5=0,acc6=0,acc7=0;
#pragma unroll
    for (int q = 0; q < 4; q++) {
        const float yq = y[q];
        const float4* wrow = (const float4*)(Wb + (size_t)(4*lane+q)*NH);
        const float4 w0 = wrow[0], w1 = wrow[1];
        acc0 = fmaf(yq, w0.x, acc0); acc1 = fmaf(yq, w0.y, acc1);
        acc2 = fmaf(yq, w0.z, acc2); acc3 = fmaf(yq, w0.w, acc3);
        acc4 = fmaf(yq, w1.x, acc4); acc5 = fmaf(yq, w1.y, acc5);
        acc6 = fmaf(yq, w1.z, acc6); acc7 = fmaf(yq, w1.w, acc7);
    }
#pragma unroll
    for (int off = 16; off; off >>= 1) {
        acc0 += __shfl_xor_sync(0xffffffffu, acc0, off);
        acc1 += __shfl_xor_sync(0xffffffffu, acc1, off);
        acc2 += __shfl_xor_sync(0xffffffffu, acc2, off);
        acc3 += __shfl_xor_sync(0xffffffffu, acc3, off);
        acc4 += __shfl_xor_sync(0xffffffffu, acc4, off);
        acc5 += __shfl_xor_sync(0xffffffffu, acc5, off);
        acc6 += __shfl_xor_sync(0xffffffffu, acc6, off);
        acc7 += __shfl_xor_sync(0xffffffffu, acc7, off);
    }
    if (lane == 0) {
        float4* op = (float4*)(g_bias + (size_t)row*NH);
        op[0] = make_float4(acc0, acc1, acc2, acc3);
        op[1] = make_float4(acc4, acc5, acc6, acc7);
    }
}

// ---------------------------------------------------------------------------
// K2b: softmax over j per (i,h); write fp16 transposed layout g_wh[h][i][j].
// ---------------------------------------------------------------------------
__global__ __launch_bounds__(256) void k2_softmax()
{
    __shared__ float sb[II][NH+1];
    const int tid = threadIdx.x;
    const int i = blockIdx.x;
    for (int idx = tid; idx < II*NH; idx += 256)
        sb[idx/NH][idx%NH] = g_bias[(size_t)i*II*NH + idx];
    __syncthreads();

    const int h = tid >> 5, lane = tid & 31;
    float v[12];
    float m = -1e30f;
#pragma unroll
    for (int q = 0; q < 12; q++) {
        v[q] = sb[lane + 32*q][h];
        m = fmaxf(m, v[q]);
    }
#pragma unroll
    for (int off = 16; off; off >>= 1)
        m = fmaxf(m, __shfl_xor_sync(0xffffffffu, m, off));
    float s = 0.f;
    float e[12];
#pragma unroll
    for (int q = 0; q < 12; q++) {
        e[q] = expf(v[q] - m);
        s += e[q];
    }
#pragma unroll
    for (int off = 16; off; off >>= 1)
        s += __shfl_xor_sync(0xffffffffu, s, off);
    const float inv = 1.f / s;
    __half* wout = g_wh + (size_t)h*II*II + (size_t)i*II;
#pragma unroll
    for (int q = 0; q < 12; q++)
        wout[lane + 32*q] = __float2half_rn(e[q] * inv);
}

// ---------------------------------------------------------------------------
// K3: tensor-core GEMM per head via mma.sync.m16n8k16 (HMMA fallback path).
// D[i, n] = sum_j w[h][i][j] * v[h][s(n)][j][c(n)],  n = s*32 + c.
// CTA tile: M=128 (i), N=128 (4 s-planes x 32 c), K=384 in 12 chunks of 32.
// 512 threads = 16 warps in 4m x 4n; warp tile 32x32 (2 m-frags x 4 n-frags).
// Smem rows padded to 80B -> conflict-free ldmatrix phases.
// A [m][k] row-major -> ldmatrix.x4 ; B [k][n] row-major -> ldmatrix.x4.trans.
// Epilogue: gate-multiply, float2 stores to g_o.  grid = (128, 3, 8).
// ---------------------------------------------------------------------------
#define K3_ROWB 80          // padded row stride (32 fp16 = 64B data + 16B pad)
#define K3_BOFF 10240       // B tile offset within one buffer (128 rows x 80B)
__global__ __launch_bounds__(512) void k3_mma()
{
    __shared__ __align__(16) char smem[2][2*K3_BOFF];   // per buf: A 10KB + B 10KB

    const int tid  = threadIdx.x;
    const int wid  = tid >> 5, lane = tid & 31;
    const int h      = blockIdx.z;
    const int i0     = blockIdx.y * 128;
    const int n0     = blockIdx.x * 128;
    const int s_base = n0 >> 5;
    const int wm = wid & 3;          // m-block: rows wm*32
    const int wn = wid >> 2;         // n-block = s-plane wn

    // staging: thread -> (row, 16B-granule)
    const int sr = tid >> 2;         // 0..127
    const int sg = tid & 3;          // 0..3
    const __half* Asrc = g_wh + ((size_t)h*II + i0 + sr)*II + sg*8;
    const int b_s = sr >> 5, b_j = sr & 31;
    const __half* Bsrc = g_vh + (((size_t)h*SS + s_base + b_s)*II + b_j)*NC + sg*8;
    const unsigned stg_off = sr*K3_ROWB + sg*16;

    // ldmatrix lane address components
    const int l8   = lane & 7;
    const int lrow8 = (lane >> 3) & 1;   // +8 rows for chunks 1,3
    const int lk16  = (lane >> 4) & 1;   // +16B (8 halves) for chunks 2,3

    const unsigned sm_base0 = smem_u32(smem[0]);
    const unsigned sm_base1 = smem_u32(smem[1]);

    // A address (relative): row = wm*32 + mf*16 + l8 + lrow8*8 ; kb = ks*32 + lk16*16
    const unsigned a_rel = (wm*32 + l8 + lrow8*8)*K3_ROWB + lk16*16;
    // B address (relative): row = wn*32 + ks*16 + lrow8*8 + l8 ; cb = np*32 + lk16*16
    const unsigned b_rel = K3_BOFF + (wn*32 + lrow8*8 + l8)*K3_ROWB + lk16*16;

    float acc[2][4][4];
#pragma unroll
    for (int mf = 0; mf < 2; mf++)
#pragma unroll
        for (int nf = 0; nf < 4; nf++)
#pragma unroll
            for (int q = 0; q < 4; q++) acc[mf][nf][q] = 0.f;

    // prologue: stage k-tile 0 into buf 0
    {
        const uint4 pa = *(const uint4*)(Asrc);
        const uint4 pb = *(const uint4*)(Bsrc);
        *(uint4*)(smem[0] + stg_off)           = pa;
        *(uint4*)(smem[0] + K3_BOFF + stg_off) = pb;
    }
    __syncthreads();

    int buf = 0;
#pragma unroll 1
    for (int kt = 0; kt < 12; kt++) {
        const bool more = (kt + 1 < 12);
        uint4 pa, pb;
        if (more) {
            const int j0 = (kt + 1) * 32;
            pa = *(const uint4*)(Asrc + j0);
            pb = *(const uint4*)(Bsrc + (size_t)j0*NC);
        }

        const unsigned base = buf ? sm_base1 : sm_base0;

        // load fragments
        unsigned af[2][2][4];    // [ks][mf][4]
        unsigned bf[2][2][4];    // [ks][np][4]  (np covers n16: two n8 frags)
#pragma unroll
        for (int ks = 0; ks < 2; ks++) {
#pragma unroll
            for (int mf = 0; mf < 2; mf++)
                ldsm_x4(af[ks][mf][0], af[ks][mf][1], af[ks][mf][2], af[ks][mf][3],
                        base + a_rel + mf*16*K3_ROWB + ks*32);
#pragma unroll
            for (int np = 0; np < 2; np++)
                ldsm_x4t(bf[ks][np][0], bf[ks][np][1], bf[ks][np][2], bf[ks][np][3],
                         base + b_rel + ks*16*K3_ROWB + np*32);
        }
        // mma
#pragma unroll
        for (int ks = 0; ks < 2; ks++)
#pragma unroll
            for (int mf = 0; mf < 2; mf++)
#pragma unroll
                for (int nf = 0; nf < 4; nf++)
                    mma16816(acc[mf][nf], af[ks][mf],
                             bf[ks][nf >> 1][(nf & 1)*2],
                             bf[ks][nf >> 1][(nf & 1)*2 + 1]);

        if (more) {
            char* nb = smem[buf ^ 1];
            *(uint4*)(nb + stg_off)           = pa;
            *(uint4*)(nb + K3_BOFF + stg_off) = pb;
        }
        __syncthreads();
        buf ^= 1;
    }

    // epilogue: gate-multiply + store (C frag: rows t/4, t/4+8; cols 2*(t%4)+{0,1})
    const int s = s_base + wn;
    const int mrow = i0 + wm*32 + (lane >> 2);
    const int cbase = 2*(lane & 3);
#pragma unroll
    for (int mf = 0; mf < 2; mf++) {
#pragma unroll
        for (int nf = 0; nf < 4; nf++) {
            const int cc = nf*8 + cbase;
            const int i_r0 = mrow + mf*16;
            {
                const size_t idx = ((size_t)s*II + i_r0)*HC + h*32 + cc;
                const float2 g = *(const float2*)(g_gate + idx);
                *(float2*)(g_o + idx) =
                    make_float2(acc[mf][nf][0]*g.x, acc[mf][nf][1]*g.y);
            }
            {
                const size_t idx = ((size_t)s*II + i_r0 + 8)*HC + h*32 + cc;
                const float2 g = *(const float2*)(g_gate + idx);
                *(float2*)(g_o + idx) =
                    make_float2(acc[mf][nf][2]*g.x, acc[mf][nf][3]*g.y);
            }
        }
    }
}

// ---------------------------------------------------------------------------
// K4: out = g_o @ W_out.  M = 196608, K = 256, N = 64.
// Tile 256x64x16, 256 threads, 8x8 micro-tile (m-pairs x dup-B), f32x2.
// Double-buffered smem: ONE __syncthreads per k-tile.  grid = 768.
// ---------------------------------------------------------------------------
__global__ __launch_bounds__(256, 2) void k4_out(
    const float* __restrict__ Wout, float* __restrict__ out)
{
    __shared__ __align__(16) float sA[2][16][260];   // [buf][k][m], m=256
    __shared__ __align__(16) float sBd[2][16][128];  // [buf][k][2n] dup B
    const int tid = threadIdx.x;
    const int r0 = blockIdx.x * 256;
    const int tx = tid & 7;      // n-group: cols tx*4..+3 and +32..+35
    const int ty = tid >> 3;     // m-group: rows ty*8..+7

    const int bk  = tid >> 4;          // B staging k
    const int bn4 = (tid & 15) * 4;    // B staging n base

    const float* Ab = g_o + (size_t)(r0 + tid)*HC;

    unsigned long long acc[4][8];      // [m-pair][n-col]
#pragma unroll
    for (int a = 0; a < 4; a++)
#pragma unroll
        for (int b = 0; b < 8; b++) acc[a][b] = 0ull;

    // prologue: fetch + stage tile 0 into buf 0
    {
        const float4 pa0 = *(const float4*)(Ab);
        const float4 pa1 = *(const float4*)(Ab + 4);
        const float4 pa2 = *(const float4*)(Ab + 8);
        const float4 pa3 = *(const float4*)(Ab + 12);
        const float4 pw  = *(const float4*)(Wout + (size_t)bk*CM + bn4);
        sA[0][0][tid]  = pa0.x; sA[0][1][tid]  = pa0.y; sA[0][2][tid]  = pa0.z; sA[0][3][tid]  = pa0.w;
        sA[0][4][tid]  = pa1.x; sA[0][5][tid]  = pa1.y; sA[0][6][tid]  = pa1.z; sA[0][7][tid]  = pa1.w;
        sA[0][8][tid]  = pa2.x; sA[0][9][tid]  = pa2.y; sA[0][10][tid] = pa2.z; sA[0][11][tid] = pa2.w;
        sA[0][12][tid] = pa3.x; sA[0][13][tid] = pa3.y; sA[0][14][tid] = pa3.z; sA[0][15][tid] = pa3.w;
        *(float4*)&sBd[0][bk][bn4*2]     = make_float4(pw.x, pw.x, pw.y, pw.y);
        *(float4*)&sBd[0][bk][bn4*2 + 4] = make_float4(pw.z, pw.z, pw.w, pw.w);
    }
    __syncthreads();

    int buf = 0;
#pragma unroll 1
    for (int k0 = 0; k0 < HC; k0 += 16) {
        const bool more = (k0 + 16 < HC);
        float4 pa0, pa1, pa2, pa3, pw;
        if (more) {
            pa0 = *(const float4*)(Ab + k0 + 16);
            pa1 = *(const float4*)(Ab + k0 + 20);
            pa2 = *(const float4*)(Ab + k0 + 24);
            pa3 = *(const float4*)(Ab + k0 + 28);
            pw  = *(const float4*)(Wout + (size_t)(k0 + 16 + bk)*CM + bn4);
        }
#pragma unroll
        for (int k = 0; k < 16; k++) {
            const ulonglong2 av0 = *(const ulonglong2*)&sA[buf][k][ty*8];
            const ulonglong2 av1 = *(const ulonglong2*)&sA[buf][k][ty*8 + 4];
            const ulonglong2 b0 = *(const ulonglong2*)&sBd[buf][k][tx*8];
            const ulonglong2 b1 = *(const ulonglong2*)&sBd[buf][k][tx*8 + 4];
            const ulonglong2 b2 = *(const ulonglong2*)&sBd[buf][k][tx*8 + 64];
            const ulonglong2 b3 = *(const ulonglong2*)&sBd[buf][k][tx*8 + 68];
            fma2(acc[0][0], av0.x, b0.x); fma2(acc[0][1], av0.x, b0.y);
            fma2(acc[0][2], av0.x, b1.x); fma2(acc[0][3], av0.x, b1.y);
            fma2(acc[0][4], av0.x, b2.x); fma2(acc[0][5], av0.x, b2.y);
            fma2(acc[0][6], av0.x, b3.x); fma2(acc[0][7], av0.x, b3.y);
            fma2(acc[1][0], av0.y, b0.x); fma2(acc[1][1], av0.y, b0.y);
            fma2(acc[1][2], av0.y, b1.x); fma2(acc[1][3], av0.y, b1.y);
            fma2(acc[1][4], av0.y, b2.x); fma2(acc[1][5], av0.y, b2.y);
            fma2(acc[1][6], av0.y, b3.x); fma2(acc[1][7], av0.y, b3.y);
            fma2(acc[2][0], av1.x, b0.x); fma2(acc[2][1], av1.x, b0.y);
            fma2(acc[2][2], av1.x, b1.x); fma2(acc[2][3], av1.x, b1.y);
            fma2(acc[2][4], av1.x, b2.x); fma2(acc[2][5], av1.x, b2.y);
            fma2(acc[2][6], av1.x, b3.x); fma2(acc[2][7], av1.x, b3.y);
            fma2(acc[3][0], av1.y, b0.x); fma2(acc[3][1], av1.y, b0.y);
            fma2(acc[3][2], av1.y, b1.x); fma2(acc[3][3], av1.y, b1.y);
            fma2(acc[3][4], av1.y, b2.x); fma2(acc[3][5], av1.y, b2.y);
            fma2(acc[3][6], av1.y, b3.x); fma2(acc[3][7], av1.y, b3.y);
        }
        if (more) {
            const int nb = buf ^ 1;
            sA[nb][0][tid]  = pa0.x; sA[nb][1][tid]  = pa0.y; sA[nb][2][tid]  = pa0.z; sA[nb][3][tid]  = pa0.w;
            sA[nb][4][tid]  = pa1.x; sA[nb][5][tid]  = pa1.y; sA[nb][6][tid]  = pa1.z; sA[nb][7][tid]  = pa1.w;
            sA[nb][8][tid]  = pa2.x; sA[nb][9][tid]  = pa2.y; sA[nb][10][tid] = pa2.z; sA[nb][11][tid] = pa2.w;
            sA[nb][12][tid] = pa3.x; sA[nb][13][tid] = pa3.y; sA[nb][14][tid] = pa3.z; sA[nb][15][tid] = pa3.w;
            *(float4*)&sBd[nb][bk][bn4*2]     = make_float4(pw.x, pw.x, pw.y, pw.y);
            *(float4*)&sBd[nb][bk][bn4*2 + 4] = make_float4(pw.z, pw.z, pw.w, pw.w);
        }
        __syncthreads();
        buf ^= 1;
    }

#pragma unroll
    for (int mp = 0; mp < 4; mp++) {
        const int m_lo = r0 + ty*8 + mp*2;
        const float2 u0 = unpk(acc[mp][0]);
        const float2 u1 = unpk(acc[mp][1]);
        const float2 u2 = unpk(acc[mp][2]);
        const float2 u3 = unpk(acc[mp][3]);
        const float2 u4 = unpk(acc[mp][4]);
        const float2 u5 = unpk(acc[mp][5]);
        const float2 u6 = unpk(acc[mp][6]);
        const float2 u7 = unpk(acc[mp][7]);
        float* o0 = out + (size_t)m_lo*CM + tx*4;
        float* o1 = out + (size_t)(m_lo+1)*CM + tx*4;
        *(float4*)(o0)      = make_float4(u0.x, u1.x, u2.x, u3.x);
        *(float4*)(o0 + 32) = make_float4(u4.x, u5.x, u6.x, u7.x);
        *(float4*)(o1)      = make_float4(u0.y, u1.y, u2.y, u3.y);
        *(float4*)(o1 + 32) = make_float4(u4.y, u5.y, u6.y, u7.y);
    }
}

// ---------------------------------------------------------------------------
extern "C" void kernel_launch(void* const* d_in, const int* in_sizes, int n_in,
                              void* d_out, int out_size)
{
    const float* msa      = (const float*)d_in[0];
    const float* pair     = (const float*)d_in[1];
    const float* ln_msa_g = (const float*)d_in[2];
    const float* ln_msa_b = (const float*)d_in[3];
    const float* ln_pair_g= (const float*)d_in[4];
    const float* ln_pair_b= (const float*)d_in[5];
    const float* W_v      = (const float*)d_in[6];
    const float* W_bias   = (const float*)d_in[7];
    const float* W_gate   = (const float*)d_in[8];
    const float* W_out    = (const float*)d_in[9];
    float* out = (float*)d_out;

    k1_msa<<<2048, 256>>>(msa, ln_msa_g, ln_msa_b, W_v, W_gate);
    k2_bias<<<18432, 256>>>(pair, ln_pair_g, ln_pair_b, W_bias);
    k2_softmax<<<II, 256>>>();
    k3_mma<<<dim3(128, 3, 8), 512>>>();
    k4_out<<<768, 256>>>(W_out, out);
}

// round 15
// speedup vs baseline: 1.9589x; 1.2562x over previous
#include <cuda_runtime.h>
#include <cuda_fp16.h>
#include <stdint.h>
#include <math.h>

#define SS 512
#define II 384
#define CM 64
#define CZ 128
#define NH 8
#define NC 32
#define HC 256

// Scratch (device globals: allocation-free rule)
__device__ __half g_vh[(size_t)NH*SS*II*NC];  // v fp16, [h][s][j][c]
__device__ __half g_wh[(size_t)NH*II*II];     // softmax weights fp16, [h][i][j]
__device__ __half g_gateh[(size_t)SS*II*HC];  // sigmoid(msa_n @ W_gate), fp16
__device__ float g_bias[(size_t)II*II*NH];    // bias[i][j][h] pre-softmax
__device__ __half g_oh[(size_t)SS*II*HC];     // gate * weighted average, fp16
__device__ __half g_wouth[(size_t)HC*CM];     // W_out fp16

// ---------------------------------------------------------------------------
// f32x2 packed-math helpers (Blackwell dual fp32 path; PTX-only)
// ---------------------------------------------------------------------------
__device__ __forceinline__ void fma2(unsigned long long& d,
                                     unsigned long long a,
                                     unsigned long long b)
{
    asm("fma.rn.f32x2 %0, %1, %2, %0;" : "+l"(d) : "l"(a), "l"(b));
}
__device__ __forceinline__ unsigned long long pack2(float lo, float hi)
{
    unsigned long long r;
    asm("mov.b64 %0, {%1, %2};" : "=l"(r)
        : "r"(__float_as_uint(lo)), "r"(__float_as_uint(hi)));
    return r;
}
__device__ __forceinline__ float2 unpk(unsigned long long v)
{
    float2 r;
    asm("mov.b64 {%0, %1}, %2;" : "=f"(r.x), "=f"(r.y) : "l"(v));
    return r;
}
__device__ __forceinline__ void add2(unsigned long long& d, unsigned long long a)
{
    asm("add.rn.f32x2 %0, %0, %1;" : "+l"(d) : "l"(a));
}

// ---------------------------------------------------------------------------
// mma.sync / ldmatrix helpers (baseline PTX, valid on compute_103)
// ---------------------------------------------------------------------------
__device__ __forceinline__ unsigned smem_u32(const void* p)
{
    unsigned a;
    asm("{ .reg .u64 t; cvta.to.shared.u64 t, %1; cvt.u32.u64 %0, t; }"
        : "=r"(a) : "l"(p));
    return a;
}
__device__ __forceinline__ void ldsm_x4(unsigned& r0, unsigned& r1,
                                        unsigned& r2, unsigned& r3, unsigned a)
{
    asm volatile("ldmatrix.sync.aligned.m8n8.x4.shared.b16 {%0,%1,%2,%3}, [%4];"
                 : "=r"(r0), "=r"(r1), "=r"(r2), "=r"(r3) : "r"(a));
}
__device__ __forceinline__ void ldsm_x4t(unsigned& r0, unsigned& r1,
                                         unsigned& r2, unsigned& r3, unsigned a)
{
    asm volatile("ldmatrix.sync.aligned.m8n8.x4.trans.shared.b16 {%0,%1,%2,%3}, [%4];"
                 : "=r"(r0), "=r"(r1), "=r"(r2), "=r"(r3) : "r"(a));
}
__device__ __forceinline__ void mma16816(float* c, const unsigned* a,
                                         unsigned b0, unsigned b1)
{
    asm volatile(
        "mma.sync.aligned.m16n8k16.row.col.f32.f16.f16.f32 "
        "{%0,%1,%2,%3}, {%4,%5,%6,%7}, {%8,%9}, {%0,%1,%2,%3};"
        : "+f"(c[0]), "+f"(c[1]), "+f"(c[2]), "+f"(c[3])
        : "r"(a[0]), "r"(a[1]), "r"(a[2]), "r"(a[3]), "r"(b0), "r"(b1));
}

// ---------------------------------------------------------------------------
// K0: convert W_out to fp16 (runs once per launch; 16384 elements).
// ---------------------------------------------------------------------------
__global__ __launch_bounds__(256) void k0_convw(const float* __restrict__ Wout)
{
    const int idx = blockIdx.x * 256 + threadIdx.x;
    if (idx < HC*CM) g_wouth[idx] = __float2half_rn(Wout[idx]);
}

// ---------------------------------------------------------------------------
// K1: msa LN + V + gate.  rows = S*I = 196608.  Block: 256 thr, 96 rows.
// Writes g_vh fp16 in [h][s][j][c] layout and g_gateh fp16 in [s][i][hc].
// ---------------------------------------------------------------------------
__global__ __launch_bounds__(256) void k1_msa(
    const float* __restrict__ msa,
    const float* __restrict__ lng, const float* __restrict__ lnb,
    const float* __restrict__ Wv,  const float* __restrict__ Wg)
{
    __shared__ __align__(16) float2 sy2[2][8][CM];   // duplicated LN rows
    const int tid = threadIdx.x;
    const int warp = tid >> 5, lane = tid & 31;

    unsigned long long w2[CM];
#pragma unroll
    for (int c = 0; c < CM; c++)
        w2[c] = pack2(Wv[c*HC + tid], Wg[c*HC + tid]);

    const float g0 = lng[lane*2], g1 = lng[lane*2+1];
    const float b0 = lnb[lane*2], b1 = lnb[lane*2+1];

    const int base = blockIdx.x * 96;

    // prologue: LN batch 0 into buf 0
    {
        const float2 x = ((const float2*)(msa + (size_t)(base + warp)*CM))[lane];
        float s1 = x.x + x.y;
        float s2 = x.x*x.x + x.y*x.y;
#pragma unroll
        for (int off = 16; off; off >>= 1) {
            s1 += __shfl_xor_sync(0xffffffffu, s1, off);
            s2 += __shfl_xor_sync(0xffffffffu, s2, off);
        }
        const float mu  = s1 * (1.f/64.f);
        const float var = s2 * (1.f/64.f) - mu*mu;
        const float rs  = rsqrtf(var + 1e-5f);
        const float y0 = (x.x - mu)*rs*g0 + b0;
        const float y1 = (x.y - mu)*rs*g1 + b1;
        sy2[0][warp][lane*2]   = make_float2(y0, y0);
        sy2[0][warp][lane*2+1] = make_float2(y1, y1);
    }
    __syncthreads();

#pragma unroll 1
    for (int it = 0; it < 12; it++) {
        const int b = it & 1;
        float2 x;
        const bool more = (it + 1 < 12);
        if (more)
            x = ((const float2*)(msa + (size_t)(base + (it+1)*8 + warp)*CM))[lane];

        // GEMV on buffer b (8 rows)
#pragma unroll 1
        for (int r = 0; r < 8; r++) {
            unsigned long long a0 = 0ull, a1 = 0ull, a2 = 0ull, a3 = 0ull;
#pragma unroll
            for (int c = 0; c < CM; c += 4) {
                const ulonglong2 q0 = *(const ulonglong2*)&sy2[b][r][c];
                const ulonglong2 q1 = *(const ulonglong2*)&sy2[b][r][c+2];
                fma2(a0, q0.x, w2[c]);
                fma2(a1, q0.y, w2[c+1]);
                fma2(a2, q1.x, w2[c+2]);
                fma2(a3, q1.y, w2[c+3]);
            }
            add2(a0, a1); add2(a2, a3); add2(a0, a2);
            const float2 res = unpk(a0);
            const int rg = base + it*8 + r;
            const int s = rg / II;
            const int ii = rg - s*II;
            g_vh[(((size_t)warp*SS + s)*II + ii)*NC + lane] = __float2half_rn(res.x);
            g_gateh[(size_t)rg*HC + tid] =
                __float2half_rn(1.f / (1.f + expf(-res.y)));
        }

        if (more) {
            float s1 = x.x + x.y;
            float s2 = x.x*x.x + x.y*x.y;
#pragma unroll
            for (int off = 16; off; off >>= 1) {
                s1 += __shfl_xor_sync(0xffffffffu, s1, off);
                s2 += __shfl_xor_sync(0xffffffffu, s2, off);
            }
            const float mu  = s1 * (1.f/64.f);
            const float var = s2 * (1.f/64.f) - mu*mu;
            const float rs  = rsqrtf(var + 1e-5f);
            const float y0 = (x.x - mu)*rs*g0 + b0;
            const float y1 = (x.y - mu)*rs*g1 + b1;
            sy2[b^1][warp][lane*2]   = make_float2(y0, y0);
            sy2[b^1][warp][lane*2+1] = make_float2(y1, y1);
        }
        __syncthreads();
    }
}

// ---------------------------------------------------------------------------
// K2a: pair LN + bias matvec.  rows = I*I = 147456, 1 warp per row.
// ---------------------------------------------------------------------------
__global__ __launch_bounds__(256) void k2_bias(
    const float* __restrict__ pair,
    const float* __restrict__ lng, const float* __restrict__ lnb,
    const float* __restrict__ Wb)
{
    const int tid = threadIdx.x, warp = tid >> 5, lane = tid & 31;
    const int row = blockIdx.x * 8 + warp;

    const float4 x = ((const float4*)(pair + (size_t)row*CZ))[lane];
    float s1 = x.x + x.y + x.z + x.w;
    float s2 = x.x*x.x + x.y*x.y + x.z*x.z + x.w*x.w;
#pragma unroll
    for (int off = 16; off; off >>= 1) {
        s1 += __shfl_xor_sync(0xffffffffu, s1, off);
        s2 += __shfl_xor_sync(0xffffffffu, s2, off);
    }
    const float mu  = s1 * (1.f/128.f);
    const float var = s2 * (1.f/128.f) - mu*mu;
    const float rs  = rsqrtf(var + 1e-5f);

    const float4 gg = ((const float4*)lng)[lane];
    const float4 bb = ((const float4*)lnb)[lane];
    float y[4];
    y[0] = (x.x - mu)*rs*gg.x + bb.x;
    y[1] = (x.y - mu)*rs*gg.y + bb.y;
    y[2] = (x.z - mu)*rs*gg.z + bb.z;
    y[3] = (x.w - mu)*rs*gg.w + bb.w;

    float acc0=0,acc1=0,acc2=0,acc3=0,acc4=0,acc5=0,acc6=0,acc7=0;
#pragma unroll
    for (int q = 0; q < 4; q++) {
        const float yq = y[q];
        const float4* wrow = (const float4*)(Wb + (size_t)(4*lane+q)*NH);
        const float4 w0 = wrow[0], w1 = wrow[1];
        acc0 = fmaf(yq, w0.x, acc0); acc1 = fmaf(yq, w0.y, acc1);
        acc2 = fmaf(yq, w0.z, acc2); acc3 = fmaf(yq, w0.w, acc3);
        acc4 = fmaf(yq, w1.x, acc4); acc5 = fmaf(yq, w1.y, acc5);
        acc6 = fmaf(yq, w1.z, acc6); acc7 = fmaf(yq, w1.w, acc7);
    }
#pragma unroll
    for (int off = 16; off; off >>= 1) {
        acc0 += __shfl_xor_sync(0xffffffffu, acc0, off);
        acc1 += __shfl_xor_sync(0xffffffffu, acc1, off);
        acc2 += __shfl_xor_sync(0xffffffffu, acc2, off);
        acc3 += __shfl_xor_sync(0xffffffffu, acc3, off);
        acc4 += __shfl_xor_sync(0xffffffffu, acc4, off);
        acc5 += __shfl_xor_sync(0xffffffffu, acc5, off);
        acc6 += __shfl_xor_sync(0xffffffffu, acc6, off);
        acc7 += __shfl_xor_sync(0xffffffffu, acc7, off);
    }
    if (lane == 0) {
        float4* op = (float4*)(g_bias + (size_t)row*NH);
        op[0] = make_float4(acc0, acc1, acc2, acc3);
        op[1] = make_float4(acc4, acc5, acc6, acc7);
    }
}

// ---------------------------------------------------------------------------
// K2b: softmax over j per (i,h); write fp16 transposed layout g_wh[h][i][j].
// ---------------------------------------------------------------------------
__global__ __launch_bounds__(256) void k2_softmax()
{
    __shared__ float sb[II][NH+1];
    const int tid = threadIdx.x;
    const int i = blockIdx.x;
    for (int idx = tid; idx < II*NH; idx += 256)
        sb[idx/NH][idx%NH] = g_bias[(size_t)i*II*NH + idx];
    __syncthreads();

    const int h = tid >> 5, lane = tid & 31;
    float v[12];
    float m = -1e30f;
#pragma unroll
    for (int q = 0; q < 12; q++) {
        v[q] = sb[lane + 32*q][h];
        m = fmaxf(m, v[q]);
    }
#pragma unroll
    for (int off = 16; off; off >>= 1)
        m = fmaxf(m, __shfl_xor_sync(0xffffffffu, m, off));
    float s = 0.f;
    float e[12];
#pragma unroll
    for (int q = 0; q < 12; q++) {
        e[q] = expf(v[q] - m);
        s += e[q];
    }
#pragma unroll
    for (int off = 16; off; off >>= 1)
        s += __shfl_xor_sync(0xffffffffu, s, off);
    const float inv = 1.f / s;
    __half* wout = g_wh + (size_t)h*II*II + (size_t)i*II;
#pragma unroll
    for (int q = 0; q < 12; q++)
        wout[lane + 32*q] = __float2half_rn(e[q] * inv);
}

// ---------------------------------------------------------------------------
// K3: tensor-core GEMM per head via mma.sync.m16n8k16.
// D[i, n] = sum_j w[h][i][j] * v[h][s(n)][j][c(n)],  n = s*32 + c.
// CTA tile: M=128 (i), N=128 (4 s-planes x 32 c), K=384 in 12 chunks of 32.
// 512 threads = 16 warps in 4m x 4n; warp tile 32x32.
// Epilogue: fp16 gate multiply, half2 stores to g_oh.  grid = (128, 3, 8).
// ---------------------------------------------------------------------------
#define K3_ROWB 80          // padded row stride (32 fp16 = 64B data + 16B pad)
#define K3_BOFF 10240       // B tile offset within one buffer (128 rows x 80B)
__global__ __launch_bounds__(512) void k3_mma()
{
    __shared__ __align__(16) char smem[2][2*K3_BOFF];   // per buf: A 10KB + B 10KB

    const int tid  = threadIdx.x;
    const int wid  = tid >> 5, lane = tid & 31;
    const int h      = blockIdx.z;
    const int i0     = blockIdx.y * 128;
    const int n0     = blockIdx.x * 128;
    const int s_base = n0 >> 5;
    const int wm = wid & 3;          // m-block: rows wm*32
    const int wn = wid >> 2;         // n-block = s-plane wn

    // staging: thread -> (row, 16B-granule)
    const int sr = tid >> 2;         // 0..127
    const int sg = tid & 3;          // 0..3
    const __half* Asrc = g_wh + ((size_t)h*II + i0 + sr)*II + sg*8;
    const int b_s = sr >> 5, b_j = sr & 31;
    const __half* Bsrc = g_vh + (((size_t)h*SS + s_base + b_s)*II + b_j)*NC + sg*8;
    const unsigned stg_off = sr*K3_ROWB + sg*16;

    // ldmatrix lane address components
    const int l8   = lane & 7;
    const int lrow8 = (lane >> 3) & 1;
    const int lk16  = (lane >> 4) & 1;

    const unsigned sm_base0 = smem_u32(smem[0]);
    const unsigned sm_base1 = smem_u32(smem[1]);

    const unsigned a_rel = (wm*32 + l8 + lrow8*8)*K3_ROWB + lk16*16;
    const unsigned b_rel = K3_BOFF + (wn*32 + lrow8*8 + l8)*K3_ROWB + lk16*16;

    float acc[2][4][4];
#pragma unroll
    for (int mf = 0; mf < 2; mf++)
#pragma unroll
        for (int nf = 0; nf < 4; nf++)
#pragma unroll
            for (int q = 0; q < 4; q++) acc[mf][nf][q] = 0.f;

    // prologue: stage k-tile 0 into buf 0
    {
        const uint4 pa = *(const uint4*)(Asrc);
        const uint4 pb = *(const uint4*)(Bsrc);
        *(uint4*)(smem[0] + stg_off)           = pa;
        *(uint4*)(smem[0] + K3_BOFF + stg_off) = pb;
    }
    __syncthreads();

    int buf = 0;
#pragma unroll 1
    for (int kt = 0; kt < 12; kt++) {
        const bool more = (kt + 1 < 12);
        uint4 pa, pb;
        if (more) {
            const int j0 = (kt + 1) * 32;
            pa = *(const uint4*)(Asrc + j0);
            pb = *(const uint4*)(Bsrc + (size_t)j0*NC);
        }

        const unsigned base = buf ? sm_base1 : sm_base0;

        unsigned af[2][2][4];
        unsigned bf[2][2][4];
#pragma unroll
        for (int ks = 0; ks < 2; ks++) {
#pragma unroll
            for (int mf = 0; mf < 2; mf++)
                ldsm_x4(af[ks][mf][0], af[ks][mf][1], af[ks][mf][2], af[ks][mf][3],
                        base + a_rel + mf*16*K3_ROWB + ks*32);
#pragma unroll
            for (int np = 0; np < 2; np++)
                ldsm_x4t(bf[ks][np][0], bf[ks][np][1], bf[ks][np][2], bf[ks][np][3],
                         base + b_rel + ks*16*K3_ROWB + np*32);
        }
#pragma unroll
        for (int ks = 0; ks < 2; ks++)
#pragma unroll
            for (int mf = 0; mf < 2; mf++)
#pragma unroll
                for (int nf = 0; nf < 4; nf++)
                    mma16816(acc[mf][nf], af[ks][mf],
                             bf[ks][nf >> 1][(nf & 1)*2],
                             bf[ks][nf >> 1][(nf & 1)*2 + 1]);

        if (more) {
            char* nb = smem[buf ^ 1];
            *(uint4*)(nb + stg_off)           = pa;
            *(uint4*)(nb + K3_BOFF + stg_off) = pb;
        }
        __syncthreads();
        buf ^= 1;
    }

    // epilogue: fp16 gate-multiply + half2 store
    const int s = s_base + wn;
    const int mrow = i0 + wm*32 + (lane >> 2);
    const int cbase = 2*(lane & 3);
#pragma unroll
    for (int mf = 0; mf < 2; mf++) {
#pragma unroll
        for (int nf = 0; nf < 4; nf++) {
            const int cc = nf*8 + cbase;
            const int i_r0 = mrow + mf*16;
            {
                const size_t idx = ((size_t)s*II + i_r0)*HC + h*32 + cc;
                const float2 g = __half22float2(*(const __half2*)(g_gateh + idx));
                *(__half2*)(g_oh + idx) = __float22half2_rn(
                    make_float2(acc[mf][nf][0]*g.x, acc[mf][nf][1]*g.y));
            }
            {
                const size_t idx = ((size_t)s*II + i_r0 + 8)*HC + h*32 + cc;
                const float2 g = __half22float2(*(const __half2*)(g_gateh + idx));
                *(__half2*)(g_oh + idx) = __float22half2_rn(
                    make_float2(acc[mf][nf][2]*g.x, acc[mf][nf][3]*g.y));
            }
        }
    }
}

// ---------------------------------------------------------------------------
// K4: out = g_oh @ g_wouth via mma.sync fp16.  M = 196608, K = 256, N = 64.
// CTA tile: M=128, N=64, K in 8 chunks of 32.  256 threads = 8 warps (4m x 2n),
// warp tile 32x32.  A rows padded to 80B, B rows to 144B.  f32 output.
// grid = 1536.
// ---------------------------------------------------------------------------
#define K4_AROWB 80          // A: 32 halves + pad
#define K4_BROWB 144         // B: 64 halves + pad
#define K4_BOFF  10240       // A tile size per buffer (128 x 80)
#define K4_BUF   (K4_BOFF + 32*K4_BROWB)   // 10240 + 4608 = 14848
__global__ __launch_bounds__(256) void k4_mma(float* __restrict__ out)
{
    __shared__ __align__(16) char smem[2][K4_BUF];

    const int tid  = threadIdx.x;
    const int wid  = tid >> 5, lane = tid & 31;
    const int m0 = blockIdx.x * 128;
    const int wm = wid & 3;          // m-block: rows wm*32
    const int wn = wid >> 2;         // n-block: cols wn*32

    // A staging: 128 rows x 64B per chunk; thread -> (row, 32B half)
    const int ar = tid >> 1;         // 0..127
    const int ah = tid & 1;          // 0..1
    const __half* Asrc = g_oh + (size_t)(m0 + ar)*HC + ah*16;
    const unsigned a_stg = ar*K4_AROWB + ah*32;

    // B staging: 32 rows x 128B per chunk; thread -> (row, 16B granule)
    const int br = tid >> 3;         // 0..31
    const int bg = tid & 7;          // 0..7
    const __half* Bsrc = g_wouth + (size_t)br*CM + bg*8;
    const unsigned b_stg = K4_BOFF + br*K4_BROWB + bg*16;

    // ldmatrix lane address components
    const int l8    = lane & 7;
    const int lrow8 = (lane >> 3) & 1;
    const int lk16  = (lane >> 4) & 1;

    const unsigned sm_base0 = smem_u32(smem[0]);
    const unsigned sm_base1 = smem_u32(smem[1]);

    const unsigned a_rel = (wm*32 + l8 + lrow8*8)*K4_AROWB + lk16*16;
    const unsigned b_rel = K4_BOFF + (lrow8*8 + l8)*K4_BROWB + wn*64 + lk16*16;

    float acc[2][4][4];
#pragma unroll
    for (int mf = 0; mf < 2; mf++)
#pragma unroll
        for (int nf = 0; nf < 4; nf++)
#pragma unroll
            for (int q = 0; q < 4; q++) acc[mf][nf][q] = 0.f;

    // prologue: stage k-chunk 0 into buf 0
    {
        const uint4 pa0 = *(const uint4*)(Asrc);
        const uint4 pa1 = *(const uint4*)(Asrc + 8);
        const uint4 pb  = *(const uint4*)(Bsrc);
        *(uint4*)(smem[0] + a_stg)      = pa0;
        *(uint4*)(smem[0] + a_stg + 16) = pa1;
        *(uint4*)(smem[0] + b_stg)      = pb;
    }
    __syncthreads();

    int buf = 0;
#pragma unroll 1
    for (int kt = 0; kt < 8; kt++) {
        const bool more = (kt + 1 < 8);
        uint4 pa0, pa1, pb;
        if (more) {
            const int k0 = (kt + 1) * 32;
            pa0 = *(const uint4*)(Asrc + k0);
            pa1 = *(const uint4*)(Asrc + k0 + 8);
            pb  = *(const uint4*)(Bsrc + (size_t)k0*CM);
        }

        const unsigned base = buf ? sm_base1 : sm_base0;

        unsigned af[2][2][4];
        unsigned bf[2][2][4];
#pragma unroll
        for (int ks = 0; ks < 2; ks++) {
#pragma unroll
            for (int mf = 0; mf < 2; mf++)
                ldsm_x4(af[ks][mf][0], af[ks][mf][1], af[ks][mf][2], af[ks][mf][3],
                        base + a_rel + mf*16*K4_AROWB + ks*32);
#pragma unroll
            for (int np = 0; np < 2; np++)
                ldsm_x4t(bf[ks][np][0], bf[ks][np][1], bf[ks][np][2], bf[ks][np][3],
                         base + b_rel + ks*16*K4_BROWB + np*32);
        }
#pragma unroll
        for (int ks = 0; ks < 2; ks++)
#pragma unroll
            for (int mf = 0; mf < 2; mf++)
#pragma unroll
                for (int nf = 0; nf < 4; nf++)
                    mma16816(acc[mf][nf], af[ks][mf],
                             bf[ks][nf >> 1][(nf & 1)*2],
                             bf[ks][nf >> 1][(nf & 1)*2 + 1]);

        if (more) {
            char* nb = smem[buf ^ 1];
            *(uint4*)(nb + a_stg)      = pa0;
            *(uint4*)(nb + a_stg + 16) = pa1;
            *(uint4*)(nb + b_stg)      = pb;
        }
        __syncthreads();
        buf ^= 1;
    }

    // epilogue: f32 stores
    const int mrow = m0 + wm*32 + (lane >> 2);
    const int cbase = wn*32 + 2*(lane & 3);
#pragma unroll
    for (int mf = 0; mf < 2; mf++) {
#pragma unroll
        for (int nf = 0; nf < 4; nf++) {
            const int col = cbase + nf*8;
            const int r0 = mrow + mf*16;
            *(float2*)(out + (size_t)r0*CM + col) =
                make_float2(acc[mf][nf][0], acc[mf][nf][1]);
            *(float2*)(out + (size_t)(r0+8)*CM + col) =
                make_float2(acc[mf][nf][2], acc[mf][nf][3]);
        }
    }
}

// ---------------------------------------------------------------------------
extern "C" void kernel_launch(void* const* d_in, const int* in_sizes, int n_in,
                              void* d_out, int out_size)
{
    const float* msa      = (const float*)d_in[0];
    const float* pair     = (const float*)d_in[1];
    const float* ln_msa_g = (const float*)d_in[2];
    const float* ln_msa_b = (const float*)d_in[3];
    const float* ln_pair_g= (const float*)d_in[4];
    const float* ln_pair_b= (const float*)d_in[5];
    const float* W_v      = (const float*)d_in[6];
    const float* W_bias   = (const float*)d_in[7];
    const float* W_gate   = (const float*)d_in[8];
    const float* W_out    = (const float*)d_in[9];
    float* out = (float*)d_out;

    k0_convw<<<64, 256>>>(W_out);
    k1_msa<<<2048, 256>>>(msa, ln_msa_g, ln_msa_b, W_v, W_gate);
    k2_bias<<<18432, 256>>>(pair, ln_pair_g, ln_pair_b, W_bias);
    k2_softmax<<<II, 256>>>();
    k3_mma<<<dim3(128, 3, 8), 512>>>();
    k4_mma<<<1536, 256>>>(out);
}

// round 16
// speedup vs baseline: 3.5152x; 1.7945x over previous
#include <cuda_runtime.h>
#include <cuda_fp16.h>
#include <stdint.h>
#include <math.h>

#define SS 512
#define II 384
#define CM 64
#define CZ 128
#define NH 8
#define NC 32
#define HC 256

// Scratch (device globals: allocation-free rule)
__device__ __half g_vh[(size_t)NH*SS*II*NC];  // v fp16, [h][s][j][c]
__device__ __half g_wh[(size_t)NH*II*II];     // softmax weights fp16, [h][i][j]
__device__ __half g_gateh[(size_t)SS*II*HC];  // sigmoid(msa_n @ W_gate), fp16
__device__ float g_bias[(size_t)II*II*NH];    // bias[i][j][h] pre-softmax
__device__ __half g_oh[(size_t)SS*II*HC];     // gate * weighted average, fp16
__device__ __half g_wouth[(size_t)HC*CM];     // W_out fp16
__device__ __half g_wvgh[(size_t)CM*512];     // [c][0:256]=Wv row, [256:512]=Wg row

// ---------------------------------------------------------------------------
// mma.sync / ldmatrix helpers (baseline PTX, valid on compute_103)
// ---------------------------------------------------------------------------
__device__ __forceinline__ unsigned smem_u32(const void* p)
{
    unsigned a;
    asm("{ .reg .u64 t; cvta.to.shared.u64 t, %1; cvt.u32.u64 %0, t; }"
        : "=r"(a) : "l"(p));
    return a;
}
__device__ __forceinline__ void ldsm_x4(unsigned& r0, unsigned& r1,
                                        unsigned& r2, unsigned& r3, unsigned a)
{
    asm volatile("ldmatrix.sync.aligned.m8n8.x4.shared.b16 {%0,%1,%2,%3}, [%4];"
                 : "=r"(r0), "=r"(r1), "=r"(r2), "=r"(r3) : "r"(a));
}
__device__ __forceinline__ void ldsm_x4t(unsigned& r0, unsigned& r1,
                                         unsigned& r2, unsigned& r3, unsigned a)
{
    asm volatile("ldmatrix.sync.aligned.m8n8.x4.trans.shared.b16 {%0,%1,%2,%3}, [%4];"
                 : "=r"(r0), "=r"(r1), "=r"(r2), "=r"(r3) : "r"(a));
}
__device__ __forceinline__ void mma16816(float* c, const unsigned* a,
                                         unsigned b0, unsigned b1)
{
    asm volatile(
        "mma.sync.aligned.m16n8k16.row.col.f32.f16.f16.f32 "
        "{%0,%1,%2,%3}, {%4,%5,%6,%7}, {%8,%9}, {%0,%1,%2,%3};"
        : "+f"(c[0]), "+f"(c[1]), "+f"(c[2]), "+f"(c[3])
        : "r"(a[0]), "r"(a[1]), "r"(a[2]), "r"(a[3]), "r"(b0), "r"(b1));
}

// ---------------------------------------------------------------------------
// K0: convert weights to fp16 (W_out, and fused [Wv|Wg]).  16384 threads.
// ---------------------------------------------------------------------------
__global__ __launch_bounds__(256) void k0_convw(
    const float* __restrict__ Wout,
    const float* __restrict__ Wv, const float* __restrict__ Wg)
{
    const int idx = blockIdx.x * 256 + threadIdx.x;
    if (idx < HC*CM) g_wouth[idx] = __float2half_rn(Wout[idx]);
    if (idx < CM*HC) {
        const int c = idx / HC, n = idx % HC;
        g_wvgh[(size_t)c*512 + n]       = __float2half_rn(Wv[idx]);
        g_wvgh[(size_t)c*512 + 256 + n] = __float2half_rn(Wg[idx]);
    }
}

// ---------------------------------------------------------------------------
// K1: LN + [V|gate] GEMM via mma.sync.  rows = S*I = 196608.
// CTA: 128 rows, 512 threads (16 warps, 4m x 4n), warp tile 32x64.
// Phase 1: LN fp32 -> fp16 A-tile in smem (144B rows).
// Phase 2: stage g_wvgh [64][512] into smem (1040B rows).
// Phase 3: two GEMM passes (K=64, 4 k16 steps): pass0 -> g_vh (scatter by
// head), pass1 -> sigmoid -> g_gateh.  grid = 1536.
// ---------------------------------------------------------------------------
#define K1_AROWB 144
#define K1_BROWB 1040
#define K1_ASZ   (128*K1_AROWB)              // 18432
#define K1_SMEM  (K1_ASZ + 64*K1_BROWB)      // 18432 + 66560 = 84992
__global__ __launch_bounds__(512) void k1_mma(
    const float* __restrict__ msa,
    const float* __restrict__ lng, const float* __restrict__ lnb)
{
    extern __shared__ char sm[];
    char* As = sm;
    char* Bs = sm + K1_ASZ;

    const int tid = threadIdx.x;
    const int wid = tid >> 5, lane = tid & 31;
    const int wm = wid & 3;          // m-block: rows wm*32
    const int wn = wid >> 2;         // n-block: cols wn*64
    const int m0 = blockIdx.x * 128;
    const int s_idx   = blockIdx.x / 3;
    const int ii_base = (blockIdx.x % 3) * 128;

    // ---- Phase 1: LN (4 threads per row, 16 floats each) ----
    {
        const int r = tid >> 2, q = tid & 3;
        const float4* src = (const float4*)(msa + (size_t)(m0 + r)*CM + q*16);
        const float4 x0 = src[0], x1 = src[1], x2 = src[2], x3 = src[3];
        float s1 = x0.x+x0.y+x0.z+x0.w + x1.x+x1.y+x1.z+x1.w
                 + x2.x+x2.y+x2.z+x2.w + x3.x+x3.y+x3.z+x3.w;
        float s2 = x0.x*x0.x+x0.y*x0.y+x0.z*x0.z+x0.w*x0.w
                 + x1.x*x1.x+x1.y*x1.y+x1.z*x1.z+x1.w*x1.w
                 + x2.x*x2.x+x2.y*x2.y+x2.z*x2.z+x2.w*x2.w
                 + x3.x*x3.x+x3.y*x3.y+x3.z*x3.z+x3.w*x3.w;
        s1 += __shfl_xor_sync(0xffffffffu, s1, 1);
        s2 += __shfl_xor_sync(0xffffffffu, s2, 1);
        s1 += __shfl_xor_sync(0xffffffffu, s1, 2);
        s2 += __shfl_xor_sync(0xffffffffu, s2, 2);
        const float mu  = s1 * (1.f/64.f);
        const float var = s2 * (1.f/64.f) - mu*mu;
        const float rs  = rsqrtf(var + 1e-5f);

        const float4* gp = (const float4*)(lng + q*16);
        const float4* bp = (const float4*)(lnb + q*16);
        const float4 gA = gp[0], gB = gp[1], gC = gp[2], gD = gp[3];
        const float4 bA = bp[0], bB = bp[1], bC = bp[2], bD = bp[3];

        __half2 h[8];
        h[0] = __float22half2_rn(make_float2((x0.x-mu)*rs*gA.x+bA.x, (x0.y-mu)*rs*gA.y+bA.y));
        h[1] = __float22half2_rn(make_float2((x0.z-mu)*rs*gA.z+bA.z, (x0.w-mu)*rs*gA.w+bA.w));
        h[2] = __float22half2_rn(make_float2((x1.x-mu)*rs*gB.x+bB.x, (x1.y-mu)*rs*gB.y+bB.y));
        h[3] = __float22half2_rn(make_float2((x1.z-mu)*rs*gB.z+bB.z, (x1.w-mu)*rs*gB.w+bB.w));
        h[4] = __float22half2_rn(make_float2((x2.x-mu)*rs*gC.x+bC.x, (x2.y-mu)*rs*gC.y+bC.y));
        h[5] = __float22half2_rn(make_float2((x2.z-mu)*rs*gC.z+bC.z, (x2.w-mu)*rs*gC.w+bC.w));
        h[6] = __float22half2_rn(make_float2((x3.x-mu)*rs*gD.x+bD.x, (x3.y-mu)*rs*gD.y+bD.y));
        h[7] = __float22half2_rn(make_float2((x3.z-mu)*rs*gD.z+bD.z, (x3.w-mu)*rs*gD.w+bD.w));
        *(uint4*)(As + r*K1_AROWB + q*32)      = *(const uint4*)&h[0];
        *(uint4*)(As + r*K1_AROWB + q*32 + 16) = *(const uint4*)&h[4];
    }

    // ---- Phase 2: stage weights [64][512] halves ----
#pragma unroll
    for (int q = 0; q < 8; q++) {
        const int u = tid + 512*q;       // 4096 granules of 16B
        const int c = u >> 6, g = u & 63;
        const uint4 val = *(const uint4*)(g_wvgh + (size_t)c*512 + g*8);
        *(uint4*)(Bs + c*K1_BROWB + g*16) = val;
    }
    __syncthreads();

    // ---- Phase 3: GEMM passes ----
    const unsigned a_base = smem_u32(As);
    const unsigned b_base = smem_u32(Bs);
    const int l8    = lane & 7;
    const int lrow8 = (lane >> 3) & 1;
    const int lk16  = (lane >> 4) & 1;
    const unsigned a_rel = (wm*32 + l8 + lrow8*8)*K1_AROWB + lk16*16;
    const unsigned b_rel = (lrow8*8 + l8)*K1_BROWB + wn*128 + lk16*16;

#pragma unroll 1
    for (int pass = 0; pass < 2; pass++) {
        float acc[2][8][4];
#pragma unroll
        for (int mf = 0; mf < 2; mf++)
#pragma unroll
            for (int nf = 0; nf < 8; nf++)
#pragma unroll
                for (int q = 0; q < 4; q++) acc[mf][nf][q] = 0.f;

#pragma unroll
        for (int ks = 0; ks < 4; ks++) {
            unsigned af[2][4];
#pragma unroll
            for (int mf = 0; mf < 2; mf++)
                ldsm_x4(af[mf][0], af[mf][1], af[mf][2], af[mf][3],
                        a_base + a_rel + mf*16*K1_AROWB + ks*32);
            unsigned bf[4][4];
#pragma unroll
            for (int np = 0; np < 4; np++)
                ldsm_x4t(bf[np][0], bf[np][1], bf[np][2], bf[np][3],
                         b_base + b_rel + pass*512 + ks*16*K1_BROWB + np*32);
#pragma unroll
            for (int mf = 0; mf < 2; mf++)
#pragma unroll
                for (int nf = 0; nf < 8; nf++)
                    mma16816(acc[mf][nf], af[mf],
                             bf[nf >> 1][(nf & 1)*2],
                             bf[nf >> 1][(nf & 1)*2 + 1]);
        }

        if (pass == 0) {
            // v epilogue: scatter to g_vh[h][s][j][c]
#pragma unroll
            for (int mf = 0; mf < 2; mf++) {
                const int ii = ii_base + wm*32 + (lane >> 2) + mf*16;
#pragma unroll
                for (int nf = 0; nf < 8; nf++) {
                    const int col = wn*64 + nf*8 + 2*(lane & 3);
                    const int h = col >> 5, c = col & 31;
                    const size_t idx =
                        (((size_t)h*SS + s_idx)*II + ii)*NC + c;
                    *(__half2*)(g_vh + idx) = __float22half2_rn(
                        make_float2(acc[mf][nf][0], acc[mf][nf][1]));
                    *(__half2*)(g_vh + idx + 8*NC) = __float22half2_rn(
                        make_float2(acc[mf][nf][2], acc[mf][nf][3]));
                }
            }
        } else {
            // gate epilogue: sigmoid -> g_gateh[rg][col]
#pragma unroll
            for (int mf = 0; mf < 2; mf++) {
                const size_t rg = (size_t)m0 + wm*32 + (lane >> 2) + mf*16;
#pragma unroll
                for (int nf = 0; nf < 8; nf++) {
                    const int col = wn*64 + nf*8 + 2*(lane & 3);
                    const float v0 = 1.f/(1.f + expf(-acc[mf][nf][0]));
                    const float v1 = 1.f/(1.f + expf(-acc[mf][nf][1]));
                    const float v2 = 1.f/(1.f + expf(-acc[mf][nf][2]));
                    const float v3 = 1.f/(1.f + expf(-acc[mf][nf][3]));
                    *(__half2*)(g_gateh + rg*HC + col) =
                        __float22half2_rn(make_float2(v0, v1));
                    *(__half2*)(g_gateh + (rg+8)*HC + col) =
                        __float22half2_rn(make_float2(v2, v3));
                }
            }
        }
    }
}

// ---------------------------------------------------------------------------
// K2a: pair LN + bias matvec.  rows = I*I = 147456, 1 warp per row.
// ---------------------------------------------------------------------------
__global__ __launch_bounds__(256) void k2_bias(
    const float* __restrict__ pair,
    const float* __restrict__ lng, const float* __restrict__ lnb,
    const float* __restrict__ Wb)
{
    const int tid = threadIdx.x, warp = tid >> 5, lane = tid & 31;
    const int row = blockIdx.x * 8 + warp;

    const float4 x = ((const float4*)(pair + (size_t)row*CZ))[lane];
    float s1 = x.x + x.y + x.z + x.w;
    float s2 = x.x*x.x + x.y*x.y + x.z*x.z + x.w*x.w;
#pragma unroll
    for (int off = 16; off; off >>= 1) {
        s1 += __shfl_xor_sync(0xffffffffu, s1, off);
        s2 += __shfl_xor_sync(0xffffffffu, s2, off);
    }
    const float mu  = s1 * (1.f/128.f);
    const float var = s2 * (1.f/128.f) - mu*mu;
    const float rs  = rsqrtf(var + 1e-5f);

    const float4 gg = ((const float4*)lng)[lane];
    const float4 bb = ((const float4*)lnb)[lane];
    float y[4];
    y[0] = (x.x - mu)*rs*gg.x + bb.x;
    y[1] = (x.y - mu)*rs*gg.y + bb.y;
    y[2] = (x.z - mu)*rs*gg.z + bb.z;
    y[3] = (x.w - mu)*rs*gg.w + bb.w;

    float acc0=0,acc1=0,acc2=0,acc3=0,acc4=0,acc5=0,acc6=0,acc7=0;
#pragma unroll
    for (int q = 0; q < 4; q++) {
        const float yq = y[q];
        const float4* wrow = (const float4*)(Wb + (size_t)(4*lane+q)*NH);
        const float4 w0 = wrow[0], w1 = wrow[1];
        acc0 = fmaf(yq, w0.x, acc0); acc1 = fmaf(yq, w0.y, acc1);
        acc2 = fmaf(yq, w0.z, acc2); acc3 = fmaf(yq, w0.w, acc3);
        acc4 = fmaf(yq, w1.x, acc4); acc5 = fmaf(yq, w1.y, acc5);
        acc6 = fmaf(yq, w1.z, acc6); acc7 = fmaf(yq, w1.w, acc7);
    }
#pragma unroll
    for (int off = 16; off; off >>= 1) {
        acc0 += __shfl_xor_sync(0xffffffffu, acc0, off);
        acc1 += __shfl_xor_sync(0xffffffffu, acc1, off);
        acc2 += __shfl_xor_sync(0xffffffffu, acc2, off);
        acc3 += __shfl_xor_sync(0xffffffffu, acc3, off);
        acc4 += __shfl_xor_sync(0xffffffffu, acc4, off);
        acc5 += __shfl_xor_sync(0xffffffffu, acc5, off);
        acc6 += __shfl_xor_sync(0xffffffffu, acc6, off);
        acc7 += __shfl_xor_sync(0xffffffffu, acc7, off);
    }
    if (lane == 0) {
        float4* op = (float4*)(g_bias + (size_t)row*NH);
        op[0] = make_float4(acc0, acc1, acc2, acc3);
        op[1] = make_float4(acc4, acc5, acc6, acc7);
    }
}

// ---------------------------------------------------------------------------
// K2b: softmax over j per (i,h); write fp16 transposed layout g_wh[h][i][j].
// ---------------------------------------------------------------------------
__global__ __launch_bounds__(256) void k2_softmax()
{
    __shared__ float sb[II][NH+1];
    const int tid = threadIdx.x;
    const int i = blockIdx.x;
    for (int idx = tid; idx < II*NH; idx += 256)
        sb[idx/NH][idx%NH] = g_bias[(size_t)i*II*NH + idx];
    __syncthreads();

    const int h = tid >> 5, lane = tid & 31;
    float v[12];
    float m = -1e30f;
#pragma unroll
    for (int q = 0; q < 12; q++) {
        v[q] = sb[lane + 32*q][h];
        m = fmaxf(m, v[q]);
    }
#pragma unroll
    for (int off = 16; off; off >>= 1)
        m = fmaxf(m, __shfl_xor_sync(0xffffffffu, m, off));
    float s = 0.f;
    float e[12];
#pragma unroll
    for (int q = 0; q < 12; q++) {
        e[q] = expf(v[q] - m);
        s += e[q];
    }
#pragma unroll
    for (int off = 16; off; off >>= 1)
        s += __shfl_xor_sync(0xffffffffu, s, off);
    const float inv = 1.f / s;
    __half* wout = g_wh + (size_t)h*II*II + (size_t)i*II;
#pragma unroll
    for (int q = 0; q < 12; q++)
        wout[lane + 32*q] = __float2half_rn(e[q] * inv);
}

// ---------------------------------------------------------------------------
// K3: tensor-core GEMM per head via mma.sync.m16n8k16.
// CTA tile: M=128 (i), N=128 (4 s-planes x 32 c), K=384 in 12 chunks of 32.
// 512 threads = 16 warps in 4m x 4n; warp tile 32x32.
// Epilogue: fp16 gate multiply, half2 stores to g_oh.  grid = (128, 3, 8).
// ---------------------------------------------------------------------------
#define K3_ROWB 80
#define K3_BOFF 10240
__global__ __launch_bounds__(512) void k3_mma()
{
    __shared__ __align__(16) char smem[2][2*K3_BOFF];

    const int tid  = threadIdx.x;
    const int wid  = tid >> 5, lane = tid & 31;
    const int h      = blockIdx.z;
    const int i0     = blockIdx.y * 128;
    const int n0     = blockIdx.x * 128;
    const int s_base = n0 >> 5;
    const int wm = wid & 3;
    const int wn = wid >> 2;

    const int sr = tid >> 2;
    const int sg = tid & 3;
    const __half* Asrc = g_wh + ((size_t)h*II + i0 + sr)*II + sg*8;
    const int b_s = sr >> 5, b_j = sr & 31;
    const __half* Bsrc = g_vh + (((size_t)h*SS + s_base + b_s)*II + b_j)*NC + sg*8;
    const unsigned stg_off = sr*K3_ROWB + sg*16;

    const int l8   = lane & 7;
    const int lrow8 = (lane >> 3) & 1;
    const int lk16  = (lane >> 4) & 1;

    const unsigned sm_base0 = smem_u32(smem[0]);
    const unsigned sm_base1 = smem_u32(smem[1]);

    const unsigned a_rel = (wm*32 + l8 + lrow8*8)*K3_ROWB + lk16*16;
    const unsigned b_rel = K3_BOFF + (wn*32 + lrow8*8 + l8)*K3_ROWB + lk16*16;

    float acc[2][4][4];
#pragma unroll
    for (int mf = 0; mf < 2; mf++)
#pragma unroll
        for (int nf = 0; nf < 4; nf++)
#pragma unroll
            for (int q = 0; q < 4; q++) acc[mf][nf][q] = 0.f;

    {
        const uint4 pa = *(const uint4*)(Asrc);
        const uint4 pb = *(const uint4*)(Bsrc);
        *(uint4*)(smem[0] + stg_off)           = pa;
        *(uint4*)(smem[0] + K3_BOFF + stg_off) = pb;
    }
    __syncthreads();

    int buf = 0;
#pragma unroll 1
    for (int kt = 0; kt < 12; kt++) {
        const bool more = (kt + 1 < 12);
        uint4 pa, pb;
        if (more) {
            const int j0 = (kt + 1) * 32;
            pa = *(const uint4*)(Asrc + j0);
            pb = *(const uint4*)(Bsrc + (size_t)j0*NC);
        }

        const unsigned base = buf ? sm_base1 : sm_base0;

        unsigned af[2][2][4];
        unsigned bf[2][2][4];
#pragma unroll
        for (int ks = 0; ks < 2; ks++) {
#pragma unroll
            for (int mf = 0; mf < 2; mf++)
                ldsm_x4(af[ks][mf][0], af[ks][mf][1], af[ks][mf][2], af[ks][mf][3],
                        base + a_rel + mf*16*K3_ROWB + ks*32);
#pragma unroll
            for (int np = 0; np < 2; np++)
                ldsm_x4t(bf[ks][np][0], bf[ks][np][1], bf[ks][np][2], bf[ks][np][3],
                         base + b_rel + ks*16*K3_ROWB + np*32);
        }
#pragma unroll
        for (int ks = 0; ks < 2; ks++)
#pragma unroll
            for (int mf = 0; mf < 2; mf++)
#pragma unroll
                for (int nf = 0; nf < 4; nf++)
                    mma16816(acc[ks ? mf : mf][nf], af[ks][mf],
                             bf[ks][nf >> 1][(nf & 1)*2],
                             bf[ks][nf >> 1][(nf & 1)*2 + 1]);

        if (more) {
            char* nb = smem[buf ^ 1];
            *(uint4*)(nb + stg_off)           = pa;
            *(uint4*)(nb + K3_BOFF + stg_off) = pb;
        }
        __syncthreads();
        buf ^= 1;
    }

    const int s = s_base + wn;
    const int mrow = i0 + wm*32 + (lane >> 2);
    const int cbase = 2*(lane & 3);
#pragma unroll
    for (int mf = 0; mf < 2; mf++) {
#pragma unroll
        for (int nf = 0; nf < 4; nf++) {
            const int cc = nf*8 + cbase;
            const int i_r0 = mrow + mf*16;
            {
                const size_t idx = ((size_t)s*II + i_r0)*HC + h*32 + cc;
                const float2 g = __half22float2(*(const __half2*)(g_gateh + idx));
                *(__half2*)(g_oh + idx) = __float22half2_rn(
                    make_float2(acc[mf][nf][0]*g.x, acc[mf][nf][1]*g.y));
            }
            {
                const size_t idx = ((size_t)s*II + i_r0 + 8)*HC + h*32 + cc;
                const float2 g = __half22float2(*(const __half2*)(g_gateh + idx));
                *(__half2*)(g_oh + idx) = __float22half2_rn(
                    make_float2(acc[mf][nf][2]*g.x, acc[mf][nf][3]*g.y));
            }
        }
    }
}

// ---------------------------------------------------------------------------
// K4: out = g_oh @ g_wouth via mma.sync fp16.  M = 196608, K = 256, N = 64.
// CTA tile: M=128, N=64, K in 8 chunks of 32.  256 threads = 8 warps (4m x 2n),
// warp tile 32x32.  grid = 1536.
// ---------------------------------------------------------------------------
#define K4_AROWB 80
#define K4_BROWB 144
#define K4_BOFF  10240
#define K4_BUF   (K4_BOFF + 32*K4_BROWB)
__global__ __launch_bounds__(256) void k4_mma(float* __restrict__ out)
{
    __shared__ __align__(16) char smem[2][K4_BUF];

    const int tid  = threadIdx.x;
    const int wid  = tid >> 5, lane = tid & 31;
    const int m0 = blockIdx.x * 128;
    const int wm = wid & 3;
    const int wn = wid >> 2;

    const int ar = tid >> 1;
    const int ah = tid & 1;
    const __half* Asrc = g_oh + (size_t)(m0 + ar)*HC + ah*16;
    const unsigned a_stg = ar*K4_AROWB + ah*32;

    const int br = tid >> 3;
    const int bg = tid & 7;
    const __half* Bsrc = g_wouth + (size_t)br*CM + bg*8;
    const unsigned b_stg = K4_BOFF + br*K4_BROWB + bg*16;

    const int l8    = lane & 7;
    const int lrow8 = (lane >> 3) & 1;
    const int lk16  = (lane >> 4) & 1;

    const unsigned sm_base0 = smem_u32(smem[0]);
    const unsigned sm_base1 = smem_u32(smem[1]);

    const unsigned a_rel = (wm*32 + l8 + lrow8*8)*K4_AROWB + lk16*16;
    const unsigned b_rel = K4_BOFF + (lrow8*8 + l8)*K4_BROWB + wn*64 + lk16*16;

    float acc[2][4][4];
#pragma unroll
    for (int mf = 0; mf < 2; mf++)
#pragma unroll
        for (int nf = 0; nf < 4; nf++)
#pragma unroll
            for (int q = 0; q < 4; q++) acc[mf][nf][q] = 0.f;

    {
        const uint4 pa0 = *(const uint4*)(Asrc);
        const uint4 pa1 = *(const uint4*)(Asrc + 8);
        const uint4 pb  = *(const uint4*)(Bsrc);
        *(uint4*)(smem[0] + a_stg)      = pa0;
        *(uint4*)(smem[0] + a_stg + 16) = pa1;
        *(uint4*)(smem[0] + b_stg)      = pb;
    }
    __syncthreads();

    int buf = 0;
#pragma unroll 1
    for (int kt = 0; kt < 8; kt++) {
        const bool more = (kt + 1 < 8);
        uint4 pa0, pa1, pb;
        if (more) {
            const int k0 = (kt + 1) * 32;
            pa0 = *(const uint4*)(Asrc + k0);
            pa1 = *(const uint4*)(Asrc + k0 + 8);
            pb  = *(const uint4*)(Bsrc + (size_t)k0*CM);
        }

        const unsigned base = buf ? sm_base1 : sm_base0;

        unsigned af[2][2][4];
        unsigned bf[2][2][4];
#pragma unroll
        for (int ks = 0; ks < 2; ks++) {
#pragma unroll
            for (int mf = 0; mf < 2; mf++)
                ldsm_x4(af[ks][mf][0], af[ks][mf][1], af[ks][mf][2], af[ks][mf][3],
                        base + a_rel + mf*16*K4_AROWB + ks*32);
#pragma unroll
            for (int np = 0; np < 2; np++)
                ldsm_x4t(bf[ks][np][0], bf[ks][np][1], bf[ks][np][2], bf[ks][np][3],
                         base + b_rel + ks*16*K4_BROWB + np*32);
        }
#pragma unroll
        for (int ks = 0; ks < 2; ks++)
#pragma unroll
            for (int mf = 0; mf < 2; mf++)
#pragma unroll
                for (int nf = 0; nf < 4; nf++)
                    mma16816(acc[mf][nf], af[ks][mf],
                             bf[ks][nf >> 1][(nf & 1)*2],
                             bf[ks][nf >> 1][(nf & 1)*2 + 1]);

        if (more) {
            char* nb = smem[buf ^ 1];
            *(uint4*)(nb + a_stg)      = pa0;
            *(uint4*)(nb + a_stg + 16) = pa1;
            *(uint4*)(nb + b_stg)      = pb;
        }
        __syncthreads();
        buf ^= 1;
    }

    const int mrow = m0 + wm*32 + (lane >> 2);
    const int cbase = wn*32 + 2*(lane & 3);
#pragma unroll
    for (int mf = 0; mf < 2; mf++) {
#pragma unroll
        for (int nf = 0; nf < 4; nf++) {
            const int col = cbase + nf*8;
            const int r0 = mrow + mf*16;
            *(float2*)(out + (size_t)r0*CM + col) =
                make_float2(acc[mf][nf][0], acc[mf][nf][1]);
            *(float2*)(out + (size_t)(r0+8)*CM + col) =
                make_float2(acc[mf][nf][2], acc[mf][nf][3]);
        }
    }
}

// ---------------------------------------------------------------------------
extern "C" void kernel_launch(void* const* d_in, const int* in_sizes, int n_in,
                              void* d_out, int out_size)
{
    const float* msa      = (const float*)d_in[0];
    const float* pair     = (const float*)d_in[1];
    const float* ln_msa_g = (const float*)d_in[2];
    const float* ln_msa_b = (const float*)d_in[3];
    const float* ln_pair_g= (const float*)d_in[4];
    const float* ln_pair_b= (const float*)d_in[5];
    const float* W_v      = (const float*)d_in[6];
    const float* W_bias   = (const float*)d_in[7];
    const float* W_gate   = (const float*)d_in[8];
    const float* W_out    = (const float*)d_in[9];
    float* out = (float*)d_out;

    cudaFuncSetAttribute(k1_mma, cudaFuncAttributeMaxDynamicSharedMemorySize,
                         K1_SMEM);

    k0_convw<<<64, 256>>>(W_out, W_v, W_gate);
    k1_mma<<<1536, 512, K1_SMEM>>>(msa, ln_msa_g, ln_msa_b);
    k2_bias<<<18432, 256>>>(pair, ln_pair_g, ln_pair_b, W_bias);
    k2_softmax<<<II, 256>>>();
    k3_mma<<<dim3(128, 3, 8), 512>>>();
    k4_mma<<<1536, 256>>>(out);
}